// round 11
// baseline (speedup 1.0000x reference)
#include <cuda_runtime.h>
#include <cuda_fp16.h>
#include <math.h>
#include <stdint.h>

#define D_MODEL 512
#define NHEADS  8
#define TSEQ    1024
#define BATCH   4
#define M_TOTAL 4096
#define N3      1536
#define KSTR    448      /* halves per packed flash row */
#define DCHUNKS 8

#define PITCH_H  24      /* fp16 chunk pitch in uint words (16 data + 8 pad), conflict-free */
#define CHWH     (64 * PITCH_H)  /* 1536 words / 6KB chunk */
/* flash: 2 Q + 2 K + 4 V = 8 chunks * 6144B = 49152B -> 4 CTA/SM */
#define FLASH_SMEM (8 * CHWH * 4)
#define LOG2E 1.4426950408889634f

// ---------------- scratch ----------------
__device__ float  g_qkv[(size_t)M_TOTAL * N3];
__device__ float  g_ctx[(size_t)M_TOTAL * D_MODEL];
__device__ float  g_res[(size_t)M_TOTAL * D_MODEL];
__device__ __half g_qh[(size_t)M_TOTAL * D_MODEL];    // query fp16 [m][k] permuted
__device__ __half g_wh[(size_t)N3 * D_MODEL];         // Wqkv^T fp16 [n][k] permuted
__device__ __half g_woh[(size_t)D_MODEL * D_MODEL];   // Wout^T fp16 [n][k] permuted
__device__ __half g_ch[(size_t)M_TOTAL * D_MODEL];    // ctx fp16 [m][k] permuted
__device__ __half g_qp[(size_t)NHEADS * M_TOTAL * KSTR];
__device__ __half g_kp[(size_t)NHEADS * M_TOTAL * KSTR];
__device__ __half g_vp[(size_t)NHEADS * DCHUNKS * BATCH * 64 * TSEQ];
__device__ float  g_mask[NHEADS][D_MODEL];
__device__ float  g_inv_scale[NHEADS];
__device__ int    g_lo[NHEADS];
__device__ int    g_hi[NHEADS];

// ---------------- helpers ----------------
__device__ __forceinline__ float ex2f(float x) {
    float y; asm("ex2.approx.f32 %0, %1;\n" : "=f"(y) : "f"(x)); return y;
}
__device__ __forceinline__ void mma_f16(float d[4], const unsigned a[4], const unsigned b[2]) {
    asm volatile(
        "mma.sync.aligned.m16n8k16.row.col.f32.f16.f16.f32 "
        "{%0,%1,%2,%3}, {%4,%5,%6,%7}, {%8,%9}, {%0,%1,%2,%3};\n"
        : "+f"(d[0]), "+f"(d[1]), "+f"(d[2]), "+f"(d[3])
        : "r"(a[0]), "r"(a[1]), "r"(a[2]), "r"(a[3]), "r"(b[0]), "r"(b[1]));
}
__device__ __forceinline__ void cp16(void* s, const void* gm) {
    unsigned sa = (unsigned)__cvta_generic_to_shared(s);
    asm volatile("cp.async.cg.shared.global [%0], [%1], 16;\n" :: "r"(sa), "l"(gm));
}
#define CP_COMMIT asm volatile("cp.async.commit_group;\n")
#define CP_WAIT0  asm volatile("cp.async.wait_group 0;\n")
#define CP_WAIT1  asm volatile("cp.async.wait_group 1;\n")

// phys word position within an 8-word k-group so fragment pairs land adjacent
__device__ __forceinline__ int permw(int lw) { return 2 * (lw & 3) + (lw >> 2); }

// ---------------- prep + fp16 converts (query, Wqkv^T, Wout^T) ----------------
__global__ __launch_bounds__(256) void prep_kernel(const float* __restrict__ hw,
                                                   const float* __restrict__ query,
                                                   const float* __restrict__ Wqkv,
                                                   const float* __restrict__ Wout) {
    int blk = blockIdx.x;
    int tid = threadIdx.x;
    if (blk == 0) {
        __shared__ float s_start[NHEADS], s_dim[NHEADS];
        if (tid == 0) {
            float m = hw[0];
            for (int h = 1; h < NHEADS; h++) m = fmaxf(m, hw[h]);
            float e[NHEADS]; float sum = 0.f;
            for (int h = 0; h < NHEADS; h++) { e[h] = expf(hw[h] - m); sum += e[h]; }
            float start = 0.f;
            for (int h = 0; h < NHEADS; h++) {
                float gate = e[h] / sum;
                float dim = 16.f + gate * (float)(D_MODEL - 16 * NHEADS);
                if (dim < 0.f) dim = 0.f;
                s_start[h] = start; s_dim[h] = dim;
                g_inv_scale[h] = rsqrtf(dim + 1e-6f);
                start += dim;
            }
        }
        __syncthreads();
        for (int d = tid; d < D_MODEL; d += 256) {
            float pos = (float)d;
            for (int h = 0; h < NHEADS; h++) {
                float l = 1.f / (1.f + expf(-(pos - s_start[h]) * 10.f));
                float r = 1.f / (1.f + expf(-(s_start[h] + s_dim[h] - pos) * 10.f));
                g_mask[h][d] = l * r;
            }
        }
        __syncthreads();
        if (tid == 0) {
            for (int h = 0; h < NHEADS; h++) {
                int lo = D_MODEL, hi = 0;
                for (int d = 0; d < D_MODEL; d++)
                    if (g_mask[h][d] > 1e-6f) { if (d < lo) lo = d; hi = d + 1; }
                if (lo >= hi) { lo = 0; hi = 0; }
                g_lo[h] = lo; g_hi[h] = hi;
            }
        }
    } else if (blk <= 64) {
        // ---- query -> g_qh fp16 [m][k] permuted ----
        int row0 = (blk - 1) * 64;
        for (int i = tid; i < 64 * 128; i += 256) {
            int r = i >> 7, f4 = i & 127;
            float4 v = *(const float4*)(query + (size_t)(row0 + r) * D_MODEL + f4 * 4);
            int k = f4 * 4;
            int chunk = k >> 5, within = k & 31;
            int group = within >> 4, lw = (within & 15) >> 1;
            __half2* dst2 = (__half2*)(g_qh + (size_t)(row0 + r) * D_MODEL);
            int base = chunk * 16 + group * 8;
            dst2[base + permw(lw)]     = __floats2half2_rn(v.x, v.y);
            dst2[base + permw(lw + 1)] = __floats2half2_rn(v.z, v.w);
        }
    } else if (blk <= 64 + 192) {
        // ---- Wqkv -> g_wh fp16 [n][k] permuted (transpose via smem) ----
        __shared__ float tile[64][65];
        int j = blk - 65;                  // 192 blocks: 8 k-tiles x 24 n-tiles
        int kt = j & 7, ntile = j >> 3;
        int k0 = kt * 64, n0 = ntile * 64;
        for (int i = tid; i < 64 * 16; i += 256) {
            int kk = i >> 4, nf = (i & 15) * 4;
            float4 v = *(const float4*)(Wqkv + (size_t)(k0 + kk) * N3 + n0 + nf);
            tile[nf][kk]     = v.x;
            tile[nf + 1][kk] = v.y;
            tile[nf + 2][kk] = v.z;
            tile[nf + 3][kk] = v.w;
        }
        __syncthreads();
        for (int i = tid; i < 64 * 32; i += 256) {
            int n = i >> 5, kw = i & 31;
            int kabs = k0 + kw * 2;
            int chunk = kabs >> 5, within = kabs & 31;
            int group = within >> 4, lw = (within & 15) >> 1;
            __half2* dst2 = (__half2*)(g_wh + (size_t)(n0 + n) * D_MODEL);
            dst2[chunk * 16 + group * 8 + permw(lw)] =
                __floats2half2_rn(tile[n][kw * 2], tile[n][kw * 2 + 1]);
        }
    } else {
        // ---- Wout -> g_woh fp16 [n][k] permuted ----
        __shared__ float tile[64][65];
        int j = blk - 65 - 192;            // 64 blocks: 8 k-tiles x 8 n-tiles
        int kt = j & 7, ntile = j >> 3;
        int k0 = kt * 64, n0 = ntile * 64;
        for (int i = tid; i < 64 * 16; i += 256) {
            int kk = i >> 4, nf = (i & 15) * 4;
            float4 v = *(const float4*)(Wout + (size_t)(k0 + kk) * D_MODEL + n0 + nf);
            tile[nf][kk]     = v.x;
            tile[nf + 1][kk] = v.y;
            tile[nf + 2][kk] = v.z;
            tile[nf + 3][kk] = v.w;
        }
        __syncthreads();
        for (int i = tid; i < 64 * 32; i += 256) {
            int n = i >> 5, kw = i & 31;
            int kabs = k0 + kw * 2;
            int chunk = kabs >> 5, within = kabs & 31;
            int group = within >> 4, lw = (within & 15) >> 1;
            __half2* dst2 = (__half2*)(g_woh + (size_t)(n0 + n) * D_MODEL);
            dst2[chunk * 16 + group * 8 + permw(lw)] =
                __floats2half2_rn(tile[n][kw * 2], tile[n][kw * 2 + 1]);
        }
    }
}

// ---------------- fp16 64x64 GEMM (A [m][k] perm, B [n][k] perm), double-buffered ------
template <int LDN>
__device__ __forceinline__ void gemm_f16_body(float c[2][4][4],
                                              const __half* Abase, const __half* Bbase,
                                              unsigned (*SA)[CHWH], unsigned (*SB)[CHWH],
                                              int tid, int wm, int wn, int g, int tig) {
    auto issue = [&](int buf, int ci) {
        #pragma unroll
        for (int it = 0; it < 2; it++) {
            int i = tid + it * 128;
            int r = i >> 2, seg = i & 3;
            cp16(&SA[buf][r * PITCH_H + seg * 4], Abase + (size_t)r * D_MODEL + ci * 32 + seg * 8);
            cp16(&SB[buf][r * PITCH_H + seg * 4], Bbase + (size_t)r * D_MODEL + ci * 32 + seg * 8);
        }
    };
    issue(0, 0); CP_COMMIT;
    const int NCH = D_MODEL / 32;
    for (int ci = 0; ci < NCH; ci++) {
        int cur = ci & 1;
        if (ci + 1 < NCH) { issue(cur ^ 1, ci + 1); CP_COMMIT; CP_WAIT1; }
        else CP_WAIT0;
        __syncthreads();
        const unsigned* A = SA[cur];
        const unsigned* B = SB[cur];
        #pragma unroll
        for (int kq = 0; kq < 2; kq++) {
            unsigned a[2][4], b[4][2];
            #pragma unroll
            for (int mt = 0; mt < 2; mt++) {
                int rowm = wm * 32 + mt * 16;
                uint2 aA = *(const uint2*)&A[(rowm + g) * PITCH_H + kq * 8 + 2 * tig];
                uint2 aB = *(const uint2*)&A[(rowm + g + 8) * PITCH_H + kq * 8 + 2 * tig];
                a[mt][0] = aA.x; a[mt][1] = aB.x; a[mt][2] = aA.y; a[mt][3] = aB.y;
            }
            #pragma unroll
            for (int nt = 0; nt < 4; nt++) {
                int rown = wn * 32 + nt * 8 + g;
                uint2 bb = *(const uint2*)&B[rown * PITCH_H + kq * 8 + 2 * tig];
                b[nt][0] = bb.x; b[nt][1] = bb.y;
            }
            #pragma unroll
            for (int mt = 0; mt < 2; mt++)
                #pragma unroll
                for (int nt = 0; nt < 4; nt++)
                    mma_f16(c[mt][nt], a[mt], b[nt]);
        }
        __syncthreads();
    }
}

// ---------------- qkv = query @ Wqkv + bqkv ----------------
__global__ __launch_bounds__(128) void qkv_gemm(const float* __restrict__ bias) {
    __shared__ unsigned SA[2][CHWH];
    __shared__ unsigned SB[2][CHWH];
    int bm = blockIdx.y * 64, bn = blockIdx.x * 64;
    int tid = threadIdx.x, w = tid >> 5, lane = tid & 31;
    int wm = w >> 1, wn = w & 1, g = lane >> 2, tig = lane & 3;
    float c[2][4][4] = {};
    gemm_f16_body<N3>(c, g_qh + (size_t)bm * D_MODEL, g_wh + (size_t)bn * D_MODEL,
                      SA, SB, tid, wm, wn, g, tig);
    #pragma unroll
    for (int mt = 0; mt < 2; mt++)
        #pragma unroll
        for (int nt = 0; nt < 4; nt++) {
            int row = bm + wm * 32 + mt * 16 + g;
            int col = bn + wn * 32 + nt * 8 + tig * 2;
            g_qkv[(size_t)row * N3 + col]           = c[mt][nt][0] + bias[col];
            g_qkv[(size_t)row * N3 + col + 1]       = c[mt][nt][1] + bias[col + 1];
            g_qkv[(size_t)(row + 8) * N3 + col]     = c[mt][nt][2] + bias[col];
            g_qkv[(size_t)(row + 8) * N3 + col + 1] = c[mt][nt][3] + bias[col + 1];
        }
}

// ---------------- pack_all: pack_qk (512) + pack_v (4096) + zero_ctx (2048) ----------------
__global__ __launch_bounds__(256) void pack_all() {
    __shared__ float tile[64][65];
    int blk = blockIdx.x;
    int tid = threadIdx.x;
    if (blk < 512) {
        int h = blk >> 6;
        int row0 = (blk & 63) * 64;
        int klo = g_lo[h] & ~31;
        int khi = (g_hi[h] + 31) & ~31; if (khi > D_MODEL) khi = D_MODEL;
        int per = (khi - klo) >> 2;
        const float* mask = g_mask[h];
        float qscale = g_inv_scale[h] * LOG2E;
        #pragma unroll
        for (int which = 0; which < 2; which++) {
            __half* dstbase = (which ? g_kp : g_qp) + ((size_t)h * M_TOTAL + row0) * KSTR;
            float sc = which ? 1.f : qscale;
            #pragma unroll
            for (int rb = 0; rb < 2; rb++) {
                int r = rb * 32 + (tid >> 3);
                const float* src = g_qkv + (size_t)(row0 + r) * N3 + which * D_MODEL;
                __half2* dst2 = (__half2*)(dstbase + (size_t)r * KSTR);
                for (int f = (tid & 7); f < per; f += 8) {
                    int k = klo + f * 4;
                    float4 v = *(const float4*)(src + k);
                    v.x *= mask[k] * sc;     v.y *= mask[k + 1] * sc;
                    v.z *= mask[k + 2] * sc; v.w *= mask[k + 3] * sc;
                    int koff = k - klo;
                    int chunk = koff >> 5;
                    int within = koff & 31;
                    int group = within >> 4;
                    int lw = (within & 15) >> 1;
                    int base = chunk * 16 + group * 8;
                    dst2[base + permw(lw)]     = __floats2half2_rn(v.x, v.y);
                    dst2[base + permw(lw + 1)] = __floats2half2_rn(v.z, v.w);
                }
            }
        }
    } else if (blk < 512 + 4096) {
        int j = blk - 512;
        int s0 = (j & 15) * 64;
        int b = (j >> 4) & 3;
        int z = j >> 6;
        int h = z >> 3, dc = z & 7;
        int d0 = dc * 64;
        if (g_hi[h] <= d0 || g_lo[h] >= d0 + 64) return;
        const float* mask = g_mask[h];
        const float* vsrc = g_qkv + (size_t)(b * TSEQ + s0) * N3 + 2 * D_MODEL + d0;
        for (int i = tid; i < 64 * 16; i += 256) {
            int s = i >> 4, dseg = (i & 15) * 4;
            float4 v = *(const float4*)(vsrc + (size_t)s * N3 + dseg);
            tile[dseg][s]     = v.x * mask[d0 + dseg];
            tile[dseg + 1][s] = v.y * mask[d0 + dseg + 1];
            tile[dseg + 2][s] = v.z * mask[d0 + dseg + 2];
            tile[dseg + 3][s] = v.w * mask[d0 + dseg + 3];
        }
        __syncthreads();
        __half* dst = g_vp + ((size_t)z * BATCH + b) * 64 * TSEQ;
        for (int i = tid; i < 64 * 32; i += 256) {
            int d = i >> 5, sw = i & 31;
            int chunk = sw >> 4;
            int wv = sw & 15;
            int group = wv >> 3, lw = wv & 7;
            __half2* dst2 = (__half2*)(dst + (size_t)d * TSEQ + s0);
            dst2[chunk * 16 + group * 8 + permw(lw)] =
                __floats2half2_rn(tile[d][2 * sw], tile[d][2 * sw + 1]);
        }
    } else {
        size_t j = (size_t)(blk - 512 - 4096) * 256 + tid;
        ((float4*)g_ctx)[j] = make_float4(0.f, 0.f, 0.f, 0.f);
    }
}

// ---------------- flash: fp16, 64 t-rows, 128 thr, 4 CTA/SM (RESCH=0) ----------------
__global__ __launch_bounds__(128, 4) void flash_kernel(const unsigned char* __restrict__ kpm) {
    extern __shared__ unsigned sm[];
    unsigned* SQb[2] = { sm,            sm + CHWH };
    unsigned* SKb[2] = { sm + 2 * CHWH, sm + 3 * CHWH };
    unsigned* SV = sm + 4 * CHWH;                // 4 V bufs
    int z = blockIdx.z, h = z >> 2, b = z & 3;
    int t0 = blockIdx.y * 64;
    int dclo = g_lo[h] >> 6, dchi = (g_hi[h] - 1) >> 6;
    int dc0 = dclo + 2 * blockIdx.x;
    if (dc0 > dchi) return;
    int nd2 = (dc0 + 1 <= dchi) ? 2 : 1;
    int klo = g_lo[h] & ~31;
    int khi = (g_hi[h] + 31) & ~31; if (khi > D_MODEL) khi = D_MODEL;
    int nch = (khi - klo) >> 5;
    const __half* qp  = g_qp + ((size_t)h * M_TOTAL + b * TSEQ + t0) * KSTR;
    const __half* kp  = g_kp + ((size_t)h * M_TOTAL + b * TSEQ) * KSTR;
    const __half* vp0 = g_vp + ((size_t)(h * 8 + dc0) * BATCH + b) * 64 * TSEQ;
    const __half* vp1 = g_vp + ((size_t)(h * 8 + dc0 + 1) * BATCH + b) * 64 * TSEQ;
    const unsigned char* kpb = kpm + b * TSEQ;
    int tid = threadIdx.x, w = tid >> 5, lane = tid & 31, g = lane >> 2, tig = lane & 3;
    int mr = w * 16;

    float o0[8][4] = {}, o1[8][4] = {};
    float m0 = -1e30f, m1 = -1e30f, l0 = 0.f, l1 = 0.f;

    for (int s0 = 0; s0 < TSEQ; s0 += 64) {
        // V prefetch
        #pragma unroll
        for (int half = 0; half < 2; half++)
            #pragma unroll
            for (int it = 0; it < 2; it++) {
                int i = tid + it * 128;
                int r = i >> 2, seg = i & 3;
                cp16(&SV[half * CHWH + r * PITCH_H + seg * 4],
                     vp0 + (size_t)r * TSEQ + s0 + half * 32 + seg * 8);
            }
        if (nd2 == 2)
            #pragma unroll
            for (int half = 0; half < 2; half++)
                #pragma unroll
                for (int it = 0; it < 2; it++) {
                    int i = tid + it * 128;
                    int r = i >> 2, seg = i & 3;
                    cp16(&SV[(2 + half) * CHWH + r * PITCH_H + seg * 4],
                         vp1 + (size_t)r * TSEQ + s0 + half * 32 + seg * 8);
                }
        CP_COMMIT;

        auto issue_chunk = [&](int buf, int ci) {
            #pragma unroll
            for (int it = 0; it < 2; it++) {
                int i = tid + it * 128;
                int r = i >> 2, seg = i & 3;
                cp16(&SKb[buf][r * PITCH_H + seg * 4], kp + (size_t)(s0 + r) * KSTR + ci * 32 + seg * 8);
                cp16(&SQb[buf][r * PITCH_H + seg * 4], qp + (size_t)r * KSTR + ci * 32 + seg * 8);
            }
        };
        issue_chunk(0, 0); CP_COMMIT;

        // ---- S = Qm . Km (fp16 MMA, log2-scaled) ----
        float c[8][4] = {};
        for (int ci = 0; ci < nch; ci++) {
            int cur = ci & 1;
            if (ci + 1 < nch) { issue_chunk(cur ^ 1, ci + 1); CP_COMMIT; CP_WAIT1; }
            else CP_WAIT0;
            __syncthreads();
            const unsigned* SQ = SQb[cur];
            const unsigned* SK = SKb[cur];
            #pragma unroll
            for (int kq = 0; kq < 2; kq++) {
                uint2 aA = *(const uint2*)&SQ[(mr + g) * PITCH_H + kq * 8 + 2 * tig];
                uint2 aB = *(const uint2*)&SQ[(mr + g + 8) * PITCH_H + kq * 8 + 2 * tig];
                unsigned a[4] = {aA.x, aB.x, aA.y, aB.y};
                #pragma unroll
                for (int nt = 0; nt < 8; nt++) {
                    uint2 bb = *(const uint2*)&SK[(nt * 8 + g) * PITCH_H + kq * 8 + 2 * tig];
                    unsigned bf[2] = {bb.x, bb.y};
                    mma_f16(c[nt], a, bf);
                }
            }
            __syncthreads();
        }
        // ---- key-padding ----
        #pragma unroll
        for (int nt = 0; nt < 8; nt++) {
            int col = s0 + nt * 8 + tig * 2;
            if (kpb[col])     { c[nt][0] = -1e9f; c[nt][2] = -1e9f; }
            if (kpb[col + 1]) { c[nt][1] = -1e9f; c[nt][3] = -1e9f; }
        }
        // ---- running max + rescale ----
        float mx0 = -1e30f, mx1 = -1e30f;
        #pragma unroll
        for (int nt = 0; nt < 8; nt++) {
            mx0 = fmaxf(mx0, fmaxf(c[nt][0], c[nt][1]));
            mx1 = fmaxf(mx1, fmaxf(c[nt][2], c[nt][3]));
        }
        mx0 = fmaxf(mx0, __shfl_xor_sync(0xffffffffu, mx0, 1));
        mx0 = fmaxf(mx0, __shfl_xor_sync(0xffffffffu, mx0, 2));
        mx1 = fmaxf(mx1, __shfl_xor_sync(0xffffffffu, mx1, 1));
        mx1 = fmaxf(mx1, __shfl_xor_sync(0xffffffffu, mx1, 2));
        float nm0 = fmaxf(m0, mx0), nm1 = fmaxf(m1, mx1);
        float al0 = ex2f(m0 - nm0), al1 = ex2f(m1 - nm1);
        m0 = nm0; m1 = nm1;
        if (al0 != 1.f || al1 != 1.f) {
            l0 *= al0; l1 *= al1;
            #pragma unroll
            for (int nt = 0; nt < 8; nt++) {
                o0[nt][0] *= al0; o0[nt][1] *= al0; o0[nt][2] *= al1; o0[nt][3] *= al1;
                o1[nt][0] *= al0; o1[nt][1] *= al0; o1[nt][2] *= al1; o1[nt][3] *= al1;
            }
        }
        // ---- exp + PV for both chunks (fp16 P; a-frag reused) ----
        unsigned* SP = SQb[0];     // safe: all warps past last S sync; reloaded next s-tile
        float rs0 = 0.f, rs1 = 0.f;
        #pragma unroll
        for (int half = 0; half < 2; half++) {
            #pragma unroll
            for (int nt = 0; nt < 4; nt++) {
                int src = half * 4 + nt;
                float e0 = ex2f(c[src][0] - m0), e1 = ex2f(c[src][1] - m0);
                float e2 = ex2f(c[src][2] - m1), e3 = ex2f(c[src][3] - m1);
                rs0 += e0 + e1; rs1 += e2 + e3;
                int wi = (nt >> 1) * 8 + 2 * tig + (nt & 1);
                __half2 hA = __floats2half2_rn(e0, e1);
                __half2 hB = __floats2half2_rn(e2, e3);
                SP[(mr + g) * PITCH_H + wi]     = *(unsigned*)&hA;
                SP[(mr + g + 8) * PITCH_H + wi] = *(unsigned*)&hB;
            }
            __syncwarp();
            const unsigned* V0 = SV + half * CHWH;
            const unsigned* V1 = SV + (2 + half) * CHWH;
            #pragma unroll
            for (int kq = 0; kq < 2; kq++) {
                uint2 aA = *(const uint2*)&SP[(mr + g) * PITCH_H + kq * 8 + 2 * tig];
                uint2 aB = *(const uint2*)&SP[(mr + g + 8) * PITCH_H + kq * 8 + 2 * tig];
                unsigned a[4] = {aA.x, aB.x, aA.y, aB.y};
                #pragma unroll
                for (int nt = 0; nt < 8; nt++) {
                    uint2 bb = *(const uint2*)&V0[(nt * 8 + g) * PITCH_H + kq * 8 + 2 * tig];
                    unsigned bf[2] = {bb.x, bb.y};
                    mma_f16(o0[nt], a, bf);
                }
                if (nd2 == 2) {
                    #pragma unroll
                    for (int nt = 0; nt < 8; nt++) {
                        uint2 bb = *(const uint2*)&V1[(nt * 8 + g) * PITCH_H + kq * 8 + 2 * tig];
                        unsigned bf[2] = {bb.x, bb.y};
                        mma_f16(o1[nt], a, bf);
                    }
                }
            }
            __syncwarp();
        }
        rs0 += __shfl_xor_sync(0xffffffffu, rs0, 1);
        rs0 += __shfl_xor_sync(0xffffffffu, rs0, 2);
        rs1 += __shfl_xor_sync(0xffffffffu, rs1, 1);
        rs1 += __shfl_xor_sync(0xffffffffu, rs1, 2);
        l0 += rs0; l1 += rs1;
        __syncthreads();
    }
    // ---- epilogue ----
    float inv0 = 1.f / l0, inv1 = 1.f / l1;
    size_t rowbase = (size_t)(b * TSEQ + t0 + mr + g) * D_MODEL;
    #pragma unroll
    for (int nt = 0; nt < 8; nt++) {
        int col = dc0 * 64 + nt * 8 + tig * 2;
        size_t r0 = rowbase + col;
        size_t r1 = r0 + (size_t)8 * D_MODEL;
        atomicAdd(&g_ctx[r0],     o0[nt][0] * inv0);
        atomicAdd(&g_ctx[r0 + 1], o0[nt][1] * inv0);
        atomicAdd(&g_ctx[r1],     o0[nt][2] * inv1);
        atomicAdd(&g_ctx[r1 + 1], o0[nt][3] * inv1);
    }
    if (nd2 == 2) {
        #pragma unroll
        for (int nt = 0; nt < 8; nt++) {
            int col = dc0 * 64 + 64 + nt * 8 + tig * 2;
            size_t r0 = rowbase + col;
            size_t r1 = r0 + (size_t)8 * D_MODEL;
            atomicAdd(&g_ctx[r0],     o1[nt][0] * inv0);
            atomicAdd(&g_ctx[r0 + 1], o1[nt][1] * inv0);
            atomicAdd(&g_ctx[r1],     o1[nt][2] * inv1);
            atomicAdd(&g_ctx[r1 + 1], o1[nt][3] * inv1);
        }
    }
}

// ---------------- ctx fp32 -> fp16 [m][k] permuted ----------------
__global__ __launch_bounds__(256) void cvt_ctx() {
    int row0 = blockIdx.x * 64;
    int tid = threadIdx.x;
    for (int i = tid; i < 64 * 128; i += 256) {
        int r = i >> 7, f4 = i & 127;
        float4 v = *(const float4*)(g_ctx + (size_t)(row0 + r) * D_MODEL + f4 * 4);
        int k = f4 * 4;
        int chunk = k >> 5, within = k & 31;
        int group = within >> 4, lw = (within & 15) >> 1;
        __half2* dst2 = (__half2*)(g_ch + (size_t)(row0 + r) * D_MODEL);
        int base = chunk * 16 + group * 8;
        dst2[base + permw(lw)]     = __floats2half2_rn(v.x, v.y);
        dst2[base + permw(lw + 1)] = __floats2half2_rn(v.z, v.w);
    }
}

// ---------------- res = ctx @ Wout + bout + query (fp16) ----------------
__global__ __launch_bounds__(128) void out_gemm(const float* __restrict__ bias,
                                                const float* __restrict__ query) {
    __shared__ unsigned SA[2][CHWH];
    __shared__ unsigned SB[2][CHWH];
    int bm = blockIdx.y * 64, bn = blockIdx.x * 64;
    int tid = threadIdx.x, w = tid >> 5, lane = tid & 31;
    int wm = w >> 1, wn = w & 1, g = lane >> 2, tig = lane & 3;
    float c[2][4][4] = {};
    gemm_f16_body<D_MODEL>(c, g_ch + (size_t)bm * D_MODEL, g_woh + (size_t)bn * D_MODEL,
                           SA, SB, tid, wm, wn, g, tig);
    #pragma unroll
    for (int mt = 0; mt < 2; mt++)
        #pragma unroll
        for (int nt = 0; nt < 4; nt++) {
            int row = bm + wm * 32 + mt * 16 + g;
            int col = bn + wn * 32 + nt * 8 + tig * 2;
            size_t i0 = (size_t)row * D_MODEL + col;
            size_t i2 = (size_t)(row + 8) * D_MODEL + col;
            g_res[i0]     = c[mt][nt][0] + bias[col]     + query[i0];
            g_res[i0 + 1] = c[mt][nt][1] + bias[col + 1] + query[i0 + 1];
            g_res[i2]     = c[mt][nt][2] + bias[col]     + query[i2];
            g_res[i2 + 1] = c[mt][nt][3] + bias[col + 1] + query[i2 + 1];
        }
}

// ---------------- layernorm ----------------
__global__ void ln_kernel(const float* __restrict__ gamma, const float* __restrict__ beta,
                          float* __restrict__ out) {
    __shared__ float shs[8];
    __shared__ float shq[8];
    int row = blockIdx.x;
    const float* x = g_res + (size_t)row * D_MODEL;
    int tid = threadIdx.x;
    float v0 = x[tid], v1 = x[tid + 256];
    float s = v0 + v1, sq = v0 * v0 + v1 * v1;
    #pragma unroll
    for (int o = 16; o > 0; o >>= 1) {
        s  += __shfl_xor_sync(0xffffffffu, s, o);
        sq += __shfl_xor_sync(0xffffffffu, sq, o);
    }
    if ((tid & 31) == 0) { shs[tid >> 5] = s; shq[tid >> 5] = sq; }
    __syncthreads();
    s = 0.f; sq = 0.f;
    #pragma unroll
    for (int w = 0; w < 8; w++) { s += shs[w]; sq += shq[w]; }
    float mu = s * (1.f / D_MODEL);
    float var = sq * (1.f / D_MODEL) - mu * mu;
    float inv = rsqrtf(var + 1e-5f);
    out[(size_t)row * D_MODEL + tid]       = (v0 - mu) * inv * gamma[tid] + beta[tid];
    out[(size_t)row * D_MODEL + tid + 256] = (v1 - mu) * inv * gamma[tid + 256] + beta[tid + 256];
}

// ---------------- launch ----------------
extern "C" void kernel_launch(void* const* d_in, const int* in_sizes, int n_in,
                              void* d_out, int out_size) {
    const float*         query = (const float*)d_in[0];
    const float*         hw    = (const float*)d_in[1];
    const float*         Wqkv  = (const float*)d_in[2];
    const float*         bqkv  = (const float*)d_in[3];
    const float*         Wout  = (const float*)d_in[4];
    const float*         bout  = (const float*)d_in[5];
    const float*         gamma = (const float*)d_in[6];
    const float*         beta  = (const float*)d_in[7];
    const unsigned char* kpm   = (const unsigned char*)d_in[8];
    float* out = (float*)d_out;

    cudaFuncSetAttribute(flash_kernel, cudaFuncAttributeMaxDynamicSharedMemorySize, FLASH_SMEM);

    prep_kernel<<<1 + 64 + 192 + 64, 256>>>(hw, query, Wqkv, Wout);     // 0
    qkv_gemm<<<dim3(N3 / 64, M_TOTAL / 64), 128>>>(bqkv);               // 1
    pack_all<<<512 + 4096 + 2048, 256>>>();                             // 2
    flash_kernel<<<dim3(4, TSEQ / 64, NHEADS * BATCH), 128, FLASH_SMEM>>>(kpm);  // 3 (profiled)
    cvt_ctx<<<M_TOTAL / 64, 256>>>();                                   // 4
    out_gemm<<<dim3(D_MODEL / 64, M_TOTAL / 64), 128>>>(bout, query);   // 5
    ln_kernel<<<M_TOTAL, 256>>>(gamma, beta, out);                      // 6
}

// round 12
// speedup vs baseline: 1.1001x; 1.1001x over previous
#include <cuda_runtime.h>
#include <cuda_fp16.h>
#include <math.h>
#include <stdint.h>

#define D_MODEL 512
#define NHEADS  8
#define TSEQ    1024
#define BATCH   4
#define M_TOTAL 4096
#define N3      1536
#define KSTR    448      /* halves per packed flash row */
#define DCHUNKS 8

#define PITCH_H  24      /* fp16 chunk pitch in uint words (16 data + 8 pad), conflict-free */
#define PITCH_MK 36
#define PITCH_KN 72
#define CHWH     (64 * PITCH_H)  /* 1536 words / 6KB chunk */
/* flash: 2 Q + 2 K + 4 V = 8 chunks * 6144B = 49152B -> 4 CTA/SM */
#define FLASH_SMEM (8 * CHWH * 4)
#define LOG2E 1.4426950408889634f

// ---------------- scratch ----------------
__device__ float  g_qkv[(size_t)M_TOTAL * N3];
__device__ float  g_ctx[(size_t)M_TOTAL * D_MODEL];
__device__ float  g_res[(size_t)M_TOTAL * D_MODEL];
__device__ __half g_qh[(size_t)M_TOTAL * D_MODEL];    // query fp16 [m][k] permuted
__device__ __half g_wh[(size_t)N3 * D_MODEL];         // Wqkv^T fp16 [n][k] permuted
__device__ __half g_qp[(size_t)NHEADS * M_TOTAL * KSTR];
__device__ __half g_kp[(size_t)NHEADS * M_TOTAL * KSTR];
__device__ __half g_vp[(size_t)NHEADS * DCHUNKS * BATCH * 64 * TSEQ];
__device__ float  g_mask[NHEADS][D_MODEL];
__device__ float  g_inv_scale[NHEADS];
__device__ int    g_lo[NHEADS];
__device__ int    g_hi[NHEADS];

// ---------------- helpers ----------------
__device__ __forceinline__ float ex2f(float x) {
    float y; asm("ex2.approx.f32 %0, %1;\n" : "=f"(y) : "f"(x)); return y;
}
__device__ __forceinline__ unsigned f2tf32(float x) {
    unsigned u; asm("cvt.rna.tf32.f32 %0, %1;\n" : "=r"(u) : "f"(x)); return u;
}
__device__ __forceinline__ void mma_tf32(float d[4], const unsigned a[4], const unsigned b[2]) {
    asm volatile(
        "mma.sync.aligned.m16n8k8.row.col.f32.tf32.tf32.f32 "
        "{%0,%1,%2,%3}, {%4,%5,%6,%7}, {%8,%9}, {%0,%1,%2,%3};\n"
        : "+f"(d[0]), "+f"(d[1]), "+f"(d[2]), "+f"(d[3])
        : "r"(a[0]), "r"(a[1]), "r"(a[2]), "r"(a[3]), "r"(b[0]), "r"(b[1]));
}
__device__ __forceinline__ void mma_f16(float d[4], const unsigned a[4], const unsigned b[2]) {
    asm volatile(
        "mma.sync.aligned.m16n8k16.row.col.f32.f16.f16.f32 "
        "{%0,%1,%2,%3}, {%4,%5,%6,%7}, {%8,%9}, {%0,%1,%2,%3};\n"
        : "+f"(d[0]), "+f"(d[1]), "+f"(d[2]), "+f"(d[3])
        : "r"(a[0]), "r"(a[1]), "r"(a[2]), "r"(a[3]), "r"(b[0]), "r"(b[1]));
}
__device__ __forceinline__ void cp16(void* s, const void* gm) {
    unsigned sa = (unsigned)__cvta_generic_to_shared(s);
    asm volatile("cp.async.cg.shared.global [%0], [%1], 16;\n" :: "r"(sa), "l"(gm));
}
#define CP_COMMIT asm volatile("cp.async.commit_group;\n")
#define CP_WAIT0  asm volatile("cp.async.wait_group 0;\n")
#define CP_WAIT1  asm volatile("cp.async.wait_group 1;\n")

// phys word position within an 8-word k-group so fragment pairs land adjacent
__device__ __forceinline__ int permw(int lw) { return 2 * (lw & 3) + (lw >> 2); }

// ---------------- prep + fp16 converts (query, Wqkv^T) ----------------
__global__ __launch_bounds__(256) void prep_kernel(const float* __restrict__ hw,
                                                   const float* __restrict__ query,
                                                   const float* __restrict__ Wqkv) {
    int blk = blockIdx.x;
    int tid = threadIdx.x;
    if (blk == 0) {
        __shared__ float s_start[NHEADS], s_dim[NHEADS];
        if (tid == 0) {
            float m = hw[0];
            for (int h = 1; h < NHEADS; h++) m = fmaxf(m, hw[h]);
            float e[NHEADS]; float sum = 0.f;
            for (int h = 0; h < NHEADS; h++) { e[h] = expf(hw[h] - m); sum += e[h]; }
            float start = 0.f;
            for (int h = 0; h < NHEADS; h++) {
                float gate = e[h] / sum;
                float dim = 16.f + gate * (float)(D_MODEL - 16 * NHEADS);
                if (dim < 0.f) dim = 0.f;
                s_start[h] = start; s_dim[h] = dim;
                g_inv_scale[h] = rsqrtf(dim + 1e-6f);
                start += dim;
            }
        }
        __syncthreads();
        for (int d = tid; d < D_MODEL; d += 256) {
            float pos = (float)d;
            for (int h = 0; h < NHEADS; h++) {
                float l = 1.f / (1.f + expf(-(pos - s_start[h]) * 10.f));
                float r = 1.f / (1.f + expf(-(s_start[h] + s_dim[h] - pos) * 10.f));
                g_mask[h][d] = l * r;
            }
        }
        __syncthreads();
        if (tid == 0) {
            for (int h = 0; h < NHEADS; h++) {
                int lo = D_MODEL, hi = 0;
                for (int d = 0; d < D_MODEL; d++)
                    if (g_mask[h][d] > 1e-6f) { if (d < lo) lo = d; hi = d + 1; }
                if (lo >= hi) { lo = 0; hi = 0; }
                g_lo[h] = lo; g_hi[h] = hi;
            }
        }
    } else if (blk <= 64) {
        // ---- query -> g_qh fp16 [m][k] permuted ----
        int row0 = (blk - 1) * 64;
        for (int i = tid; i < 64 * 128; i += 256) {
            int r = i >> 7, f4 = i & 127;
            float4 v = *(const float4*)(query + (size_t)(row0 + r) * D_MODEL + f4 * 4);
            int k = f4 * 4;
            int chunk = k >> 5, within = k & 31;
            int group = within >> 4, lw = (within & 15) >> 1;
            __half2* dst2 = (__half2*)(g_qh + (size_t)(row0 + r) * D_MODEL);
            int base = chunk * 16 + group * 8;
            dst2[base + permw(lw)]     = __floats2half2_rn(v.x, v.y);
            dst2[base + permw(lw + 1)] = __floats2half2_rn(v.z, v.w);
        }
    } else {
        // ---- Wqkv -> g_wh fp16 [n][k] permuted (transpose via smem) ----
        __shared__ float tile[64][65];
        int j = blk - 65;                  // 192 blocks: 8 k-tiles x 24 n-tiles
        int kt = j & 7, ntile = j >> 3;
        int k0 = kt * 64, n0 = ntile * 64;
        for (int i = tid; i < 64 * 16; i += 256) {
            int kk = i >> 4, nf = (i & 15) * 4;
            float4 v = *(const float4*)(Wqkv + (size_t)(k0 + kk) * N3 + n0 + nf);
            tile[nf][kk]     = v.x;
            tile[nf + 1][kk] = v.y;
            tile[nf + 2][kk] = v.z;
            tile[nf + 3][kk] = v.w;
        }
        __syncthreads();
        for (int i = tid; i < 64 * 32; i += 256) {
            int n = i >> 5, kw = i & 31;
            int kabs = k0 + kw * 2;
            int chunk = kabs >> 5, within = kabs & 31;
            int group = within >> 4, lw = (within & 15) >> 1;
            __half2* dst2 = (__half2*)(g_wh + (size_t)(n0 + n) * D_MODEL);
            dst2[chunk * 16 + group * 8 + permw(lw)] =
                __floats2half2_rn(tile[n][kw * 2], tile[n][kw * 2 + 1]);
        }
    }
}

// ---------------- qkv = query @ Wqkv + bqkv (fp16 MMA, double-buffered) ----------------
__global__ __launch_bounds__(128) void qkv_gemm(const float* __restrict__ bias) {
    __shared__ unsigned SA[2][CHWH];
    __shared__ unsigned SB[2][CHWH];
    int bm = blockIdx.y * 64, bn = blockIdx.x * 64;
    int tid = threadIdx.x, w = tid >> 5, lane = tid & 31;
    int wm = w >> 1, wn = w & 1, g = lane >> 2, tig = lane & 3;
    float c[2][4][4] = {};
    const __half* Abase = g_qh + (size_t)bm * D_MODEL;
    const __half* Bbase = g_wh + (size_t)bn * D_MODEL;
    auto issue = [&](int buf, int ci) {
        #pragma unroll
        for (int it = 0; it < 2; it++) {
            int i = tid + it * 128;
            int r = i >> 2, seg = i & 3;
            cp16(&SA[buf][r * PITCH_H + seg * 4], Abase + (size_t)r * D_MODEL + ci * 32 + seg * 8);
            cp16(&SB[buf][r * PITCH_H + seg * 4], Bbase + (size_t)r * D_MODEL + ci * 32 + seg * 8);
        }
    };
    issue(0, 0); CP_COMMIT;
    const int NCH = D_MODEL / 32;
    for (int ci = 0; ci < NCH; ci++) {
        int cur = ci & 1;
        if (ci + 1 < NCH) { issue(cur ^ 1, ci + 1); CP_COMMIT; CP_WAIT1; }
        else CP_WAIT0;
        __syncthreads();
        const unsigned* A = SA[cur];
        const unsigned* B = SB[cur];
        #pragma unroll
        for (int kq = 0; kq < 2; kq++) {
            unsigned a[2][4], b[4][2];
            #pragma unroll
            for (int mt = 0; mt < 2; mt++) {
                int rowm = wm * 32 + mt * 16;
                uint2 aA = *(const uint2*)&A[(rowm + g) * PITCH_H + kq * 8 + 2 * tig];
                uint2 aB = *(const uint2*)&A[(rowm + g + 8) * PITCH_H + kq * 8 + 2 * tig];
                a[mt][0] = aA.x; a[mt][1] = aB.x; a[mt][2] = aA.y; a[mt][3] = aB.y;
            }
            #pragma unroll
            for (int nt = 0; nt < 4; nt++) {
                int rown = wn * 32 + nt * 8 + g;
                uint2 bb = *(const uint2*)&B[rown * PITCH_H + kq * 8 + 2 * tig];
                b[nt][0] = bb.x; b[nt][1] = bb.y;
            }
            #pragma unroll
            for (int mt = 0; mt < 2; mt++)
                #pragma unroll
                for (int nt = 0; nt < 4; nt++)
                    mma_f16(c[mt][nt], a[mt], b[nt]);
        }
        __syncthreads();
    }
    #pragma unroll
    for (int mt = 0; mt < 2; mt++)
        #pragma unroll
        for (int nt = 0; nt < 4; nt++) {
            int row = bm + wm * 32 + mt * 16 + g;
            int col = bn + wn * 32 + nt * 8 + tig * 2;
            g_qkv[(size_t)row * N3 + col]           = c[mt][nt][0] + bias[col];
            g_qkv[(size_t)row * N3 + col + 1]       = c[mt][nt][1] + bias[col + 1];
            g_qkv[(size_t)(row + 8) * N3 + col]     = c[mt][nt][2] + bias[col];
            g_qkv[(size_t)(row + 8) * N3 + col + 1] = c[mt][nt][3] + bias[col + 1];
        }
}

// ---------------- pack_all: pack_qk (512) + pack_v (4096) + zero_ctx (2048) ----------------
__global__ __launch_bounds__(256) void pack_all() {
    __shared__ float tile[64][65];
    int blk = blockIdx.x;
    int tid = threadIdx.x;
    if (blk < 512) {
        int h = blk >> 6;
        int row0 = (blk & 63) * 64;
        int klo = g_lo[h] & ~31;
        int khi = (g_hi[h] + 31) & ~31; if (khi > D_MODEL) khi = D_MODEL;
        int per = (khi - klo) >> 2;
        const float* mask = g_mask[h];
        float qscale = g_inv_scale[h] * LOG2E;
        #pragma unroll
        for (int which = 0; which < 2; which++) {
            __half* dstbase = (which ? g_kp : g_qp) + ((size_t)h * M_TOTAL + row0) * KSTR;
            float sc = which ? 1.f : qscale;
            #pragma unroll
            for (int rb = 0; rb < 2; rb++) {
                int r = rb * 32 + (tid >> 3);
                const float* src = g_qkv + (size_t)(row0 + r) * N3 + which * D_MODEL;
                __half2* dst2 = (__half2*)(dstbase + (size_t)r * KSTR);
                for (int f = (tid & 7); f < per; f += 8) {
                    int k = klo + f * 4;
                    float4 v = *(const float4*)(src + k);
                    v.x *= mask[k] * sc;     v.y *= mask[k + 1] * sc;
                    v.z *= mask[k + 2] * sc; v.w *= mask[k + 3] * sc;
                    int koff = k - klo;
                    int chunk = koff >> 5;
                    int within = koff & 31;
                    int group = within >> 4;
                    int lw = (within & 15) >> 1;
                    int base = chunk * 16 + group * 8;
                    dst2[base + permw(lw)]     = __floats2half2_rn(v.x, v.y);
                    dst2[base + permw(lw + 1)] = __floats2half2_rn(v.z, v.w);
                }
            }
        }
    } else if (blk < 512 + 4096) {
        int j = blk - 512;
        int s0 = (j & 15) * 64;
        int b = (j >> 4) & 3;
        int z = j >> 6;
        int h = z >> 3, dc = z & 7;
        int d0 = dc * 64;
        if (g_hi[h] <= d0 || g_lo[h] >= d0 + 64) return;
        const float* mask = g_mask[h];
        const float* vsrc = g_qkv + (size_t)(b * TSEQ + s0) * N3 + 2 * D_MODEL + d0;
        for (int i = tid; i < 64 * 16; i += 256) {
            int s = i >> 4, dseg = (i & 15) * 4;
            float4 v = *(const float4*)(vsrc + (size_t)s * N3 + dseg);
            tile[dseg][s]     = v.x * mask[d0 + dseg];
            tile[dseg + 1][s] = v.y * mask[d0 + dseg + 1];
            tile[dseg + 2][s] = v.z * mask[d0 + dseg + 2];
            tile[dseg + 3][s] = v.w * mask[d0 + dseg + 3];
        }
        __syncthreads();
        __half* dst = g_vp + ((size_t)z * BATCH + b) * 64 * TSEQ;
        for (int i = tid; i < 64 * 32; i += 256) {
            int d = i >> 5, sw = i & 31;
            int chunk = sw >> 4;
            int wv = sw & 15;
            int group = wv >> 3, lw = wv & 7;
            __half2* dst2 = (__half2*)(dst + (size_t)d * TSEQ + s0);
            dst2[chunk * 16 + group * 8 + permw(lw)] =
                __floats2half2_rn(tile[d][2 * sw], tile[d][2 * sw + 1]);
        }
    } else {
        size_t j = (size_t)(blk - 512 - 4096) * 256 + tid;
        ((float4*)g_ctx)[j] = make_float4(0.f, 0.f, 0.f, 0.f);
    }
}

// ---------------- flash: fp16, 64 t-rows, 128 thr, 4 CTA/SM (RESCH=0) ----------------
__global__ __launch_bounds__(128, 4) void flash_kernel(const unsigned char* __restrict__ kpm) {
    extern __shared__ unsigned sm[];
    unsigned* SQb[2] = { sm,            sm + CHWH };
    unsigned* SKb[2] = { sm + 2 * CHWH, sm + 3 * CHWH };
    unsigned* SV = sm + 4 * CHWH;                // 4 V bufs
    int z = blockIdx.z, h = z >> 2, b = z & 3;
    int t0 = blockIdx.y * 64;
    int dclo = g_lo[h] >> 6, dchi = (g_hi[h] - 1) >> 6;
    int dc0 = dclo + 2 * blockIdx.x;
    if (dc0 > dchi) return;
    int nd2 = (dc0 + 1 <= dchi) ? 2 : 1;
    int klo = g_lo[h] & ~31;
    int khi = (g_hi[h] + 31) & ~31; if (khi > D_MODEL) khi = D_MODEL;
    int nch = (khi - klo) >> 5;
    const __half* qp  = g_qp + ((size_t)h * M_TOTAL + b * TSEQ + t0) * KSTR;
    const __half* kp  = g_kp + ((size_t)h * M_TOTAL + b * TSEQ) * KSTR;
    const __half* vp0 = g_vp + ((size_t)(h * 8 + dc0) * BATCH + b) * 64 * TSEQ;
    const __half* vp1 = g_vp + ((size_t)(h * 8 + dc0 + 1) * BATCH + b) * 64 * TSEQ;
    const unsigned char* kpb = kpm + b * TSEQ;
    int tid = threadIdx.x, w = tid >> 5, lane = tid & 31, g = lane >> 2, tig = lane & 3;
    int mr = w * 16;

    float o0[8][4] = {}, o1[8][4] = {};
    float m0 = -1e30f, m1 = -1e30f, l0 = 0.f, l1 = 0.f;

    for (int s0 = 0; s0 < TSEQ; s0 += 64) {
        // V prefetch
        #pragma unroll
        for (int half = 0; half < 2; half++)
            #pragma unroll
            for (int it = 0; it < 2; it++) {
                int i = tid + it * 128;
                int r = i >> 2, seg = i & 3;
                cp16(&SV[half * CHWH + r * PITCH_H + seg * 4],
                     vp0 + (size_t)r * TSEQ + s0 + half * 32 + seg * 8);
            }
        if (nd2 == 2)
            #pragma unroll
            for (int half = 0; half < 2; half++)
                #pragma unroll
                for (int it = 0; it < 2; it++) {
                    int i = tid + it * 128;
                    int r = i >> 2, seg = i & 3;
                    cp16(&SV[(2 + half) * CHWH + r * PITCH_H + seg * 4],
                         vp1 + (size_t)r * TSEQ + s0 + half * 32 + seg * 8);
                }
        CP_COMMIT;

        auto issue_chunk = [&](int buf, int ci) {
            #pragma unroll
            for (int it = 0; it < 2; it++) {
                int i = tid + it * 128;
                int r = i >> 2, seg = i & 3;
                cp16(&SKb[buf][r * PITCH_H + seg * 4], kp + (size_t)(s0 + r) * KSTR + ci * 32 + seg * 8);
                cp16(&SQb[buf][r * PITCH_H + seg * 4], qp + (size_t)r * KSTR + ci * 32 + seg * 8);
            }
        };
        issue_chunk(0, 0); CP_COMMIT;

        // ---- S = Qm . Km (fp16 MMA, log2-scaled) ----
        float c[8][4] = {};
        for (int ci = 0; ci < nch; ci++) {
            int cur = ci & 1;
            if (ci + 1 < nch) { issue_chunk(cur ^ 1, ci + 1); CP_COMMIT; CP_WAIT1; }
            else CP_WAIT0;
            __syncthreads();
            const unsigned* SQ = SQb[cur];
            const unsigned* SK = SKb[cur];
            #pragma unroll
            for (int kq = 0; kq < 2; kq++) {
                uint2 aA = *(const uint2*)&SQ[(mr + g) * PITCH_H + kq * 8 + 2 * tig];
                uint2 aB = *(const uint2*)&SQ[(mr + g + 8) * PITCH_H + kq * 8 + 2 * tig];
                unsigned a[4] = {aA.x, aB.x, aA.y, aB.y};
                #pragma unroll
                for (int nt = 0; nt < 8; nt++) {
                    uint2 bb = *(const uint2*)&SK[(nt * 8 + g) * PITCH_H + kq * 8 + 2 * tig];
                    unsigned bf[2] = {bb.x, bb.y};
                    mma_f16(c[nt], a, bf);
                }
            }
            __syncthreads();
        }
        // ---- key-padding ----
        #pragma unroll
        for (int nt = 0; nt < 8; nt++) {
            int col = s0 + nt * 8 + tig * 2;
            if (kpb[col])     { c[nt][0] = -1e9f; c[nt][2] = -1e9f; }
            if (kpb[col + 1]) { c[nt][1] = -1e9f; c[nt][3] = -1e9f; }
        }
        // ---- running max + rescale ----
        float mx0 = -1e30f, mx1 = -1e30f;
        #pragma unroll
        for (int nt = 0; nt < 8; nt++) {
            mx0 = fmaxf(mx0, fmaxf(c[nt][0], c[nt][1]));
            mx1 = fmaxf(mx1, fmaxf(c[nt][2], c[nt][3]));
        }
        mx0 = fmaxf(mx0, __shfl_xor_sync(0xffffffffu, mx0, 1));
        mx0 = fmaxf(mx0, __shfl_xor_sync(0xffffffffu, mx0, 2));
        mx1 = fmaxf(mx1, __shfl_xor_sync(0xffffffffu, mx1, 1));
        mx1 = fmaxf(mx1, __shfl_xor_sync(0xffffffffu, mx1, 2));
        float nm0 = fmaxf(m0, mx0), nm1 = fmaxf(m1, mx1);
        float al0 = ex2f(m0 - nm0), al1 = ex2f(m1 - nm1);
        m0 = nm0; m1 = nm1;
        if (al0 != 1.f || al1 != 1.f) {
            l0 *= al0; l1 *= al1;
            #pragma unroll
            for (int nt = 0; nt < 8; nt++) {
                o0[nt][0] *= al0; o0[nt][1] *= al0; o0[nt][2] *= al1; o0[nt][3] *= al1;
                o1[nt][0] *= al0; o1[nt][1] *= al0; o1[nt][2] *= al1; o1[nt][3] *= al1;
            }
        }
        // ---- exp + PV for both chunks (fp16 P; a-frag reused) ----
        unsigned* SP = SQb[0];     // safe: all warps past last S sync; reloaded next s-tile
        float rs0 = 0.f, rs1 = 0.f;
        #pragma unroll
        for (int half = 0; half < 2; half++) {
            #pragma unroll
            for (int nt = 0; nt < 4; nt++) {
                int src = half * 4 + nt;
                float e0 = ex2f(c[src][0] - m0), e1 = ex2f(c[src][1] - m0);
                float e2 = ex2f(c[src][2] - m1), e3 = ex2f(c[src][3] - m1);
                rs0 += e0 + e1; rs1 += e2 + e3;
                int wi = (nt >> 1) * 8 + 2 * tig + (nt & 1);
                __half2 hA = __floats2half2_rn(e0, e1);
                __half2 hB = __floats2half2_rn(e2, e3);
                SP[(mr + g) * PITCH_H + wi]     = *(unsigned*)&hA;
                SP[(mr + g + 8) * PITCH_H + wi] = *(unsigned*)&hB;
            }
            __syncwarp();
            const unsigned* V0 = SV + half * CHWH;
            const unsigned* V1 = SV + (2 + half) * CHWH;
            #pragma unroll
            for (int kq = 0; kq < 2; kq++) {
                uint2 aA = *(const uint2*)&SP[(mr + g) * PITCH_H + kq * 8 + 2 * tig];
                uint2 aB = *(const uint2*)&SP[(mr + g + 8) * PITCH_H + kq * 8 + 2 * tig];
                unsigned a[4] = {aA.x, aB.x, aA.y, aB.y};
                #pragma unroll
                for (int nt = 0; nt < 8; nt++) {
                    uint2 bb = *(const uint2*)&V0[(nt * 8 + g) * PITCH_H + kq * 8 + 2 * tig];
                    unsigned bf[2] = {bb.x, bb.y};
                    mma_f16(o0[nt], a, bf);
                }
                if (nd2 == 2) {
                    #pragma unroll
                    for (int nt = 0; nt < 8; nt++) {
                        uint2 bb = *(const uint2*)&V1[(nt * 8 + g) * PITCH_H + kq * 8 + 2 * tig];
                        unsigned bf[2] = {bb.x, bb.y};
                        mma_f16(o1[nt], a, bf);
                    }
                }
            }
            __syncwarp();
        }
        rs0 += __shfl_xor_sync(0xffffffffu, rs0, 1);
        rs0 += __shfl_xor_sync(0xffffffffu, rs0, 2);
        rs1 += __shfl_xor_sync(0xffffffffu, rs1, 1);
        rs1 += __shfl_xor_sync(0xffffffffu, rs1, 2);
        l0 += rs0; l1 += rs1;
        __syncthreads();
    }
    // ---- epilogue ----
    float inv0 = 1.f / l0, inv1 = 1.f / l1;
    size_t rowbase = (size_t)(b * TSEQ + t0 + mr + g) * D_MODEL;
    #pragma unroll
    for (int nt = 0; nt < 8; nt++) {
        int col = dc0 * 64 + nt * 8 + tig * 2;
        size_t r0 = rowbase + col;
        size_t r1 = r0 + (size_t)8 * D_MODEL;
        atomicAdd(&g_ctx[r0],     o0[nt][0] * inv0);
        atomicAdd(&g_ctx[r0 + 1], o0[nt][1] * inv0);
        atomicAdd(&g_ctx[r1],     o0[nt][2] * inv1);
        atomicAdd(&g_ctx[r1 + 1], o0[nt][3] * inv1);
    }
    if (nd2 == 2) {
        #pragma unroll
        for (int nt = 0; nt < 8; nt++) {
            int col = dc0 * 64 + 64 + nt * 8 + tig * 2;
            size_t r0 = rowbase + col;
            size_t r1 = r0 + (size_t)8 * D_MODEL;
            atomicAdd(&g_ctx[r0],     o1[nt][0] * inv0);
            atomicAdd(&g_ctx[r0 + 1], o1[nt][1] * inv0);
            atomicAdd(&g_ctx[r1],     o1[nt][2] * inv1);
            atomicAdd(&g_ctx[r1 + 1], o1[nt][3] * inv1);
        }
    }
}

// ---------------- res = ctx @ Wout + bout + query (tf32) ----------------
__device__ __forceinline__ void mma_tile_kn(float c[2][4][4], const unsigned* As, const unsigned* Bs,
                                            int wm, int wn, int g, int tig) {
    #pragma unroll
    for (int kq = 0; kq < 32; kq += 8) {
        unsigned a[2][4], b[4][2];
        #pragma unroll
        for (int mt = 0; mt < 2; mt++) {
            int mr = wm * 32 + mt * 16;
            a[mt][0] = As[(mr + g) * PITCH_MK + kq + tig];
            a[mt][1] = As[(mr + g + 8) * PITCH_MK + kq + tig];
            a[mt][2] = As[(mr + g) * PITCH_MK + kq + tig + 4];
            a[mt][3] = As[(mr + g + 8) * PITCH_MK + kq + tig + 4];
        }
        #pragma unroll
        for (int nt = 0; nt < 4; nt++) {
            int nr = wn * 32 + nt * 8;
            b[nt][0] = Bs[(kq + tig) * PITCH_KN + nr + g];
            b[nt][1] = Bs[(kq + tig + 4) * PITCH_KN + nr + g];
        }
        #pragma unroll
        for (int mt = 0; mt < 2; mt++)
            #pragma unroll
            for (int nt = 0; nt < 4; nt++)
                mma_tf32(c[mt][nt], a[mt], b[nt]);
    }
}

__global__ __launch_bounds__(128) void out_gemm(const float* __restrict__ W,
                                                const float* __restrict__ bias,
                                                const float* __restrict__ query) {
    __shared__ float As[2][64 * PITCH_MK];
    __shared__ float Bs[2][32 * PITCH_KN];
    int bm = blockIdx.y * 64, bn = blockIdx.x * 64;
    int tid = threadIdx.x, w = tid >> 5, lane = tid & 31;
    int wm = w >> 1, wn = w & 1, g = lane >> 2, tig = lane & 3;
    float c[2][4][4] = {};
    const float* Abase = g_ctx + (size_t)bm * D_MODEL;
    const float* Wbase = W + bn;
    auto issue = [&](int buf, int k0) {
        #pragma unroll
        for (int it = 0; it < 4; it++) {
            int i = tid + it * 128;
            int r = i >> 3, q = (i & 7) * 4;
            cp16(&As[buf][r * PITCH_MK + q], Abase + (size_t)r * D_MODEL + k0 + q);
        }
        #pragma unroll
        for (int it = 0; it < 4; it++) {
            int i = tid + it * 128;
            int k = i >> 4, q = (i & 15) * 4;
            cp16(&Bs[buf][k * PITCH_KN + q], Wbase + (size_t)(k0 + k) * D_MODEL + q);
        }
    };
    issue(0, 0); CP_COMMIT;
    const int NCH = D_MODEL / 32;
    for (int ci = 0; ci < NCH; ci++) {
        int cur = ci & 1;
        if (ci + 1 < NCH) { issue(cur ^ 1, (ci + 1) * 32); CP_COMMIT; CP_WAIT1; }
        else CP_WAIT0;
        __syncthreads();
        mma_tile_kn(c, (const unsigned*)As[cur], (const unsigned*)Bs[cur], wm, wn, g, tig);
        __syncthreads();
    }
    #pragma unroll
    for (int mt = 0; mt < 2; mt++)
        #pragma unroll
        for (int nt = 0; nt < 4; nt++) {
            int row = bm + wm * 32 + mt * 16 + g;
            int col = bn + wn * 32 + nt * 8 + tig * 2;
            size_t i0 = (size_t)row * D_MODEL + col;
            size_t i2 = (size_t)(row + 8) * D_MODEL + col;
            g_res[i0]     = c[mt][nt][0] + bias[col]     + query[i0];
            g_res[i0 + 1] = c[mt][nt][1] + bias[col + 1] + query[i0 + 1];
            g_res[i2]     = c[mt][nt][2] + bias[col]     + query[i2];
            g_res[i2 + 1] = c[mt][nt][3] + bias[col + 1] + query[i2 + 1];
        }
}

// ---------------- layernorm ----------------
__global__ void ln_kernel(const float* __restrict__ gamma, const float* __restrict__ beta,
                          float* __restrict__ out) {
    __shared__ float shs[8];
    __shared__ float shq[8];
    int row = blockIdx.x;
    const float* x = g_res + (size_t)row * D_MODEL;
    int tid = threadIdx.x;
    float v0 = x[tid], v1 = x[tid + 256];
    float s = v0 + v1, sq = v0 * v0 + v1 * v1;
    #pragma unroll
    for (int o = 16; o > 0; o >>= 1) {
        s  += __shfl_xor_sync(0xffffffffu, s, o);
        sq += __shfl_xor_sync(0xffffffffu, sq, o);
    }
    if ((tid & 31) == 0) { shs[tid >> 5] = s; shq[tid >> 5] = sq; }
    __syncthreads();
    s = 0.f; sq = 0.f;
    #pragma unroll
    for (int w = 0; w < 8; w++) { s += shs[w]; sq += shq[w]; }
    float mu = s * (1.f / D_MODEL);
    float var = sq * (1.f / D_MODEL) - mu * mu;
    float inv = rsqrtf(var + 1e-5f);
    out[(size_t)row * D_MODEL + tid]       = (v0 - mu) * inv * gamma[tid] + beta[tid];
    out[(size_t)row * D_MODEL + tid + 256] = (v1 - mu) * inv * gamma[tid + 256] + beta[tid + 256];
}

// ---------------- launch ----------------
extern "C" void kernel_launch(void* const* d_in, const int* in_sizes, int n_in,
                              void* d_out, int out_size) {
    const float*         query = (const float*)d_in[0];
    const float*         hw    = (const float*)d_in[1];
    const float*         Wqkv  = (const float*)d_in[2];
    const float*         bqkv  = (const float*)d_in[3];
    const float*         Wout  = (const float*)d_in[4];
    const float*         bout  = (const float*)d_in[5];
    const float*         gamma = (const float*)d_in[6];
    const float*         beta  = (const float*)d_in[7];
    const unsigned char* kpm   = (const unsigned char*)d_in[8];
    float* out = (float*)d_out;

    cudaFuncSetAttribute(flash_kernel, cudaFuncAttributeMaxDynamicSharedMemorySize, FLASH_SMEM);

    prep_kernel<<<1 + 64 + 192, 256>>>(hw, query, Wqkv);                // 0
    qkv_gemm<<<dim3(N3 / 64, M_TOTAL / 64), 128>>>(bqkv);               // 1
    pack_all<<<512 + 4096 + 2048, 256>>>();                             // 2
    flash_kernel<<<dim3(4, TSEQ / 64, NHEADS * BATCH), 128, FLASH_SMEM>>>(kpm);  // 3 (profiled)
    out_gemm<<<dim3(D_MODEL / 64, M_TOTAL / 64), 128>>>(Wout, bout, query);      // 4
    ln_kernel<<<M_TOTAL, 256>>>(gamma, beta, out);                      // 5
}

// round 13
// speedup vs baseline: 1.1434x; 1.0394x over previous
#include <cuda_runtime.h>
#include <cuda_fp16.h>
#include <math.h>
#include <stdint.h>

#define D_MODEL 512
#define NHEADS  8
#define TSEQ    1024
#define BATCH   4
#define M_TOTAL 4096
#define N3      1536
#define KSTR    448      /* halves per packed flash row */
#define DCHUNKS 8

#define PITCH_H  24      /* fp16 chunk pitch in uint words (16 data + 8 pad), conflict-free */
#define PITCH_MK 36
#define PITCH_KN 72
#define CHWH     (64 * PITCH_H)  /* 1536 words / 6KB chunk */
/* flash: 2 Q + 2 K + 4 V = 8 chunks * 6144B = 49152B -> 4 CTA/SM */
#define FLASH_SMEM (8 * CHWH * 4)
#define LOG2E 1.4426950408889634f

// ---------------- scratch ----------------
__device__ float  g_qkv[(size_t)M_TOTAL * N3];
__device__ float  g_ctx[(size_t)M_TOTAL * D_MODEL];
__device__ float  g_res[(size_t)M_TOTAL * D_MODEL];
__device__ __half g_qh[(size_t)M_TOTAL * D_MODEL];    // query fp16 [m][k] permuted
__device__ __half g_wh[(size_t)N3 * D_MODEL];         // Wqkv^T fp16 [n][k] permuted
__device__ __half g_qp[(size_t)NHEADS * M_TOTAL * KSTR];
__device__ __half g_kp[(size_t)NHEADS * M_TOTAL * KSTR];
__device__ __half g_vp[(size_t)NHEADS * DCHUNKS * BATCH * 64 * TSEQ];
__device__ float  g_mask[NHEADS][D_MODEL];
__device__ float  g_inv_scale[NHEADS];
__device__ int    g_lo[NHEADS];
__device__ int    g_hi[NHEADS];

// ---------------- helpers ----------------
__device__ __forceinline__ float ex2f(float x) {
    float y; asm("ex2.approx.f32 %0, %1;\n" : "=f"(y) : "f"(x)); return y;
}
__device__ __forceinline__ void mma_tf32(float d[4], const unsigned a[4], const unsigned b[2]) {
    asm volatile(
        "mma.sync.aligned.m16n8k8.row.col.f32.tf32.tf32.f32 "
        "{%0,%1,%2,%3}, {%4,%5,%6,%7}, {%8,%9}, {%0,%1,%2,%3};\n"
        : "+f"(d[0]), "+f"(d[1]), "+f"(d[2]), "+f"(d[3])
        : "r"(a[0]), "r"(a[1]), "r"(a[2]), "r"(a[3]), "r"(b[0]), "r"(b[1]));
}
__device__ __forceinline__ void mma_f16(float d[4], const unsigned a[4], const unsigned b[2]) {
    asm volatile(
        "mma.sync.aligned.m16n8k16.row.col.f32.f16.f16.f32 "
        "{%0,%1,%2,%3}, {%4,%5,%6,%7}, {%8,%9}, {%0,%1,%2,%3};\n"
        : "+f"(d[0]), "+f"(d[1]), "+f"(d[2]), "+f"(d[3])
        : "r"(a[0]), "r"(a[1]), "r"(a[2]), "r"(a[3]), "r"(b[0]), "r"(b[1]));
}
__device__ __forceinline__ void cp16(void* s, const void* gm) {
    unsigned sa = (unsigned)__cvta_generic_to_shared(s);
    asm volatile("cp.async.cg.shared.global [%0], [%1], 16;\n" :: "r"(sa), "l"(gm));
}
#define CP_COMMIT asm volatile("cp.async.commit_group;\n")
#define CP_WAIT0  asm volatile("cp.async.wait_group 0;\n")
#define CP_WAIT1  asm volatile("cp.async.wait_group 1;\n")

// phys word position within an 8-word k-group so fragment pairs land adjacent
__device__ __forceinline__ int permw(int lw) { return 2 * (lw & 3) + (lw >> 2); }

// ---------------- prep + fp16 converts (query, Wqkv^T) ----------------
__global__ __launch_bounds__(256) void prep_kernel(const float* __restrict__ hw,
                                                   const float* __restrict__ query,
                                                   const float* __restrict__ Wqkv) {
    int blk = blockIdx.x;
    int tid = threadIdx.x;
    if (blk == 0) {
        __shared__ float s_start[NHEADS], s_dim[NHEADS];
        if (tid == 0) {
            float m = hw[0];
            for (int h = 1; h < NHEADS; h++) m = fmaxf(m, hw[h]);
            float e[NHEADS]; float sum = 0.f;
            for (int h = 0; h < NHEADS; h++) { e[h] = expf(hw[h] - m); sum += e[h]; }
            float start = 0.f;
            for (int h = 0; h < NHEADS; h++) {
                float gate = e[h] / sum;
                float dim = 16.f + gate * (float)(D_MODEL - 16 * NHEADS);
                if (dim < 0.f) dim = 0.f;
                s_start[h] = start; s_dim[h] = dim;
                g_inv_scale[h] = rsqrtf(dim + 1e-6f);
                start += dim;
            }
        }
        __syncthreads();
        for (int d = tid; d < D_MODEL; d += 256) {
            float pos = (float)d;
            for (int h = 0; h < NHEADS; h++) {
                float l = 1.f / (1.f + expf(-(pos - s_start[h]) * 10.f));
                float r = 1.f / (1.f + expf(-(s_start[h] + s_dim[h] - pos) * 10.f));
                g_mask[h][d] = l * r;
            }
        }
        __syncthreads();
        if (tid == 0) {
            for (int h = 0; h < NHEADS; h++) {
                int lo = D_MODEL, hi = 0;
                for (int d = 0; d < D_MODEL; d++)
                    if (g_mask[h][d] > 1e-6f) { if (d < lo) lo = d; hi = d + 1; }
                if (lo >= hi) { lo = 0; hi = 0; }
                g_lo[h] = lo; g_hi[h] = hi;
            }
        }
    } else if (blk <= 64) {
        // ---- query -> g_qh fp16 [m][k] permuted ----
        int row0 = (blk - 1) * 64;
        for (int i = tid; i < 64 * 128; i += 256) {
            int r = i >> 7, f4 = i & 127;
            float4 v = *(const float4*)(query + (size_t)(row0 + r) * D_MODEL + f4 * 4);
            int k = f4 * 4;
            int chunk = k >> 5, within = k & 31;
            int group = within >> 4, lw = (within & 15) >> 1;
            __half2* dst2 = (__half2*)(g_qh + (size_t)(row0 + r) * D_MODEL);
            int base = chunk * 16 + group * 8;
            dst2[base + permw(lw)]     = __floats2half2_rn(v.x, v.y);
            dst2[base + permw(lw + 1)] = __floats2half2_rn(v.z, v.w);
        }
    } else {
        // ---- Wqkv -> g_wh fp16 [n][k] permuted (transpose via smem) ----
        __shared__ float tile[64][65];
        int j = blk - 65;                  // 192 blocks: 8 k-tiles x 24 n-tiles
        int kt = j & 7, ntile = j >> 3;
        int k0 = kt * 64, n0 = ntile * 64;
        for (int i = tid; i < 64 * 16; i += 256) {
            int kk = i >> 4, nf = (i & 15) * 4;
            float4 v = *(const float4*)(Wqkv + (size_t)(k0 + kk) * N3 + n0 + nf);
            tile[nf][kk]     = v.x;
            tile[nf + 1][kk] = v.y;
            tile[nf + 2][kk] = v.z;
            tile[nf + 3][kk] = v.w;
        }
        __syncthreads();
        for (int i = tid; i < 64 * 32; i += 256) {
            int n = i >> 5, kw = i & 31;
            int kabs = k0 + kw * 2;
            int chunk = kabs >> 5, within = kabs & 31;
            int group = within >> 4, lw = (within & 15) >> 1;
            __half2* dst2 = (__half2*)(g_wh + (size_t)(n0 + n) * D_MODEL);
            dst2[chunk * 16 + group * 8 + permw(lw)] =
                __floats2half2_rn(tile[n][kw * 2], tile[n][kw * 2 + 1]);
        }
    }
}

// ---------------- qkv = query @ Wqkv + bqkv (fp16 MMA, double-buffered) ----------------
__global__ __launch_bounds__(128) void qkv_gemm(const float* __restrict__ bias) {
    __shared__ unsigned SA[2][CHWH];
    __shared__ unsigned SB[2][CHWH];
    int bm = blockIdx.y * 64, bn = blockIdx.x * 64;
    int tid = threadIdx.x, w = tid >> 5, lane = tid & 31;
    int wm = w >> 1, wn = w & 1, g = lane >> 2, tig = lane & 3;
    float c[2][4][4] = {};
    const __half* Abase = g_qh + (size_t)bm * D_MODEL;
    const __half* Bbase = g_wh + (size_t)bn * D_MODEL;
    auto issue = [&](int buf, int ci) {
        #pragma unroll
        for (int it = 0; it < 2; it++) {
            int i = tid + it * 128;
            int r = i >> 2, seg = i & 3;
            cp16(&SA[buf][r * PITCH_H + seg * 4], Abase + (size_t)r * D_MODEL + ci * 32 + seg * 8);
            cp16(&SB[buf][r * PITCH_H + seg * 4], Bbase + (size_t)r * D_MODEL + ci * 32 + seg * 8);
        }
    };
    issue(0, 0); CP_COMMIT;
    const int NCH = D_MODEL / 32;
    for (int ci = 0; ci < NCH; ci++) {
        int cur = ci & 1;
        if (ci + 1 < NCH) { issue(cur ^ 1, ci + 1); CP_COMMIT; CP_WAIT1; }
        else CP_WAIT0;
        __syncthreads();
        const unsigned* A = SA[cur];
        const unsigned* B = SB[cur];
        #pragma unroll
        for (int kq = 0; kq < 2; kq++) {
            unsigned a[2][4], b[4][2];
            #pragma unroll
            for (int mt = 0; mt < 2; mt++) {
                int rowm = wm * 32 + mt * 16;
                uint2 aA = *(const uint2*)&A[(rowm + g) * PITCH_H + kq * 8 + 2 * tig];
                uint2 aB = *(const uint2*)&A[(rowm + g + 8) * PITCH_H + kq * 8 + 2 * tig];
                a[mt][0] = aA.x; a[mt][1] = aB.x; a[mt][2] = aA.y; a[mt][3] = aB.y;
            }
            #pragma unroll
            for (int nt = 0; nt < 4; nt++) {
                int rown = wn * 32 + nt * 8 + g;
                uint2 bb = *(const uint2*)&B[rown * PITCH_H + kq * 8 + 2 * tig];
                b[nt][0] = bb.x; b[nt][1] = bb.y;
            }
            #pragma unroll
            for (int mt = 0; mt < 2; mt++)
                #pragma unroll
                for (int nt = 0; nt < 4; nt++)
                    mma_f16(c[mt][nt], a[mt], b[nt]);
        }
        __syncthreads();
    }
    #pragma unroll
    for (int mt = 0; mt < 2; mt++)
        #pragma unroll
        for (int nt = 0; nt < 4; nt++) {
            int row = bm + wm * 32 + mt * 16 + g;
            int col = bn + wn * 32 + nt * 8 + tig * 2;
            g_qkv[(size_t)row * N3 + col]           = c[mt][nt][0] + bias[col];
            g_qkv[(size_t)row * N3 + col + 1]       = c[mt][nt][1] + bias[col + 1];
            g_qkv[(size_t)(row + 8) * N3 + col]     = c[mt][nt][2] + bias[col];
            g_qkv[(size_t)(row + 8) * N3 + col + 1] = c[mt][nt][3] + bias[col + 1];
        }
}

// ---------------- pack_all: pack_qk (512) + pack_v (4096) + zero_ctx (2048) ----------------
__global__ __launch_bounds__(256) void pack_all() {
    __shared__ float tile[64][65];
    int blk = blockIdx.x;
    int tid = threadIdx.x;
    if (blk < 512) {
        int h = blk >> 6;
        int row0 = (blk & 63) * 64;
        int klo = g_lo[h] & ~31;
        int khi = (g_hi[h] + 31) & ~31; if (khi > D_MODEL) khi = D_MODEL;
        int per = (khi - klo) >> 2;
        const float* mask = g_mask[h];
        float qscale = g_inv_scale[h] * LOG2E;
        #pragma unroll
        for (int which = 0; which < 2; which++) {
            __half* dstbase = (which ? g_kp : g_qp) + ((size_t)h * M_TOTAL + row0) * KSTR;
            float sc = which ? 1.f : qscale;
            #pragma unroll
            for (int rb = 0; rb < 2; rb++) {
                int r = rb * 32 + (tid >> 3);
                const float* src = g_qkv + (size_t)(row0 + r) * N3 + which * D_MODEL;
                __half2* dst2 = (__half2*)(dstbase + (size_t)r * KSTR);
                for (int f = (tid & 7); f < per; f += 8) {
                    int k = klo + f * 4;
                    float4 v = *(const float4*)(src + k);
                    v.x *= mask[k] * sc;     v.y *= mask[k + 1] * sc;
                    v.z *= mask[k + 2] * sc; v.w *= mask[k + 3] * sc;
                    int koff = k - klo;
                    int chunk = koff >> 5;
                    int within = koff & 31;
                    int group = within >> 4;
                    int lw = (within & 15) >> 1;
                    int base = chunk * 16 + group * 8;
                    dst2[base + permw(lw)]     = __floats2half2_rn(v.x, v.y);
                    dst2[base + permw(lw + 1)] = __floats2half2_rn(v.z, v.w);
                }
            }
        }
    } else if (blk < 512 + 4096) {
        int j = blk - 512;
        int s0 = (j & 15) * 64;
        int b = (j >> 4) & 3;
        int z = j >> 6;
        int h = z >> 3, dc = z & 7;
        int d0 = dc * 64;
        if (g_hi[h] <= d0 || g_lo[h] >= d0 + 64) return;
        const float* mask = g_mask[h];
        const float* vsrc = g_qkv + (size_t)(b * TSEQ + s0) * N3 + 2 * D_MODEL + d0;
        for (int i = tid; i < 64 * 16; i += 256) {
            int s = i >> 4, dseg = (i & 15) * 4;
            float4 v = *(const float4*)(vsrc + (size_t)s * N3 + dseg);
            tile[dseg][s]     = v.x * mask[d0 + dseg];
            tile[dseg + 1][s] = v.y * mask[d0 + dseg + 1];
            tile[dseg + 2][s] = v.z * mask[d0 + dseg + 2];
            tile[dseg + 3][s] = v.w * mask[d0 + dseg + 3];
        }
        __syncthreads();
        __half* dst = g_vp + ((size_t)z * BATCH + b) * 64 * TSEQ;
        for (int i = tid; i < 64 * 32; i += 256) {
            int d = i >> 5, sw = i & 31;
            int chunk = sw >> 4;
            int wv = sw & 15;
            int group = wv >> 3, lw = wv & 7;
            __half2* dst2 = (__half2*)(dst + (size_t)d * TSEQ + s0);
            dst2[chunk * 16 + group * 8 + permw(lw)] =
                __floats2half2_rn(tile[d][2 * sw], tile[d][2 * sw + 1]);
        }
    } else {
        size_t j = (size_t)(blk - 512 - 4096) * 256 + tid;
        ((float4*)g_ctx)[j] = make_float4(0.f, 0.f, 0.f, 0.f);
    }
}

// ---------------- flash: fp16, 64 t-rows, 128 thr, 4 CTA/SM, P in registers ----------------
__global__ __launch_bounds__(128, 4) void flash_kernel(const unsigned char* __restrict__ kpm) {
    extern __shared__ unsigned sm[];
    unsigned* SQb[2] = { sm,            sm + CHWH };
    unsigned* SKb[2] = { sm + 2 * CHWH, sm + 3 * CHWH };
    unsigned* SV = sm + 4 * CHWH;                // 4 V bufs (2 d-chunks x 2 s-halves)
    int z = blockIdx.z, h = z >> 2, b = z & 3;
    int t0 = blockIdx.y * 64;
    int dclo = g_lo[h] >> 6, dchi = (g_hi[h] - 1) >> 6;
    int dc0 = dclo + 2 * blockIdx.x;
    if (dc0 > dchi) return;
    int nd2 = (dc0 + 1 <= dchi) ? 2 : 1;
    int klo = g_lo[h] & ~31;
    int khi = (g_hi[h] + 31) & ~31; if (khi > D_MODEL) khi = D_MODEL;
    int nch = (khi - klo) >> 5;
    const __half* qp  = g_qp + ((size_t)h * M_TOTAL + b * TSEQ + t0) * KSTR;
    const __half* kp  = g_kp + ((size_t)h * M_TOTAL + b * TSEQ) * KSTR;
    const __half* vp0 = g_vp + ((size_t)(h * 8 + dc0) * BATCH + b) * 64 * TSEQ;
    const __half* vp1 = g_vp + ((size_t)(h * 8 + dc0 + 1) * BATCH + b) * 64 * TSEQ;
    const unsigned char* kpb = kpm + b * TSEQ;
    int tid = threadIdx.x, w = tid >> 5, lane = tid & 31, g = lane >> 2, tig = lane & 3;
    int mr = w * 16;

    float o0[8][4] = {}, o1[8][4] = {};
    float m0 = -1e30f, m1 = -1e30f, l0 = 0.f, l1 = 0.f;

    for (int s0 = 0; s0 < TSEQ; s0 += 64) {
        // V prefetch
        #pragma unroll
        for (int half = 0; half < 2; half++)
            #pragma unroll
            for (int it = 0; it < 2; it++) {
                int i = tid + it * 128;
                int r = i >> 2, seg = i & 3;
                cp16(&SV[half * CHWH + r * PITCH_H + seg * 4],
                     vp0 + (size_t)r * TSEQ + s0 + half * 32 + seg * 8);
            }
        if (nd2 == 2)
            #pragma unroll
            for (int half = 0; half < 2; half++)
                #pragma unroll
                for (int it = 0; it < 2; it++) {
                    int i = tid + it * 128;
                    int r = i >> 2, seg = i & 3;
                    cp16(&SV[(2 + half) * CHWH + r * PITCH_H + seg * 4],
                         vp1 + (size_t)r * TSEQ + s0 + half * 32 + seg * 8);
                }
        CP_COMMIT;

        auto issue_chunk = [&](int buf, int ci) {
            #pragma unroll
            for (int it = 0; it < 2; it++) {
                int i = tid + it * 128;
                int r = i >> 2, seg = i & 3;
                cp16(&SKb[buf][r * PITCH_H + seg * 4], kp + (size_t)(s0 + r) * KSTR + ci * 32 + seg * 8);
                cp16(&SQb[buf][r * PITCH_H + seg * 4], qp + (size_t)r * KSTR + ci * 32 + seg * 8);
            }
        };
        issue_chunk(0, 0); CP_COMMIT;

        // ---- S = Qm . Km (fp16 MMA, log2-scaled) ----
        float c[8][4] = {};
        for (int ci = 0; ci < nch; ci++) {
            int cur = ci & 1;
            if (ci + 1 < nch) { issue_chunk(cur ^ 1, ci + 1); CP_COMMIT; CP_WAIT1; }
            else CP_WAIT0;
            __syncthreads();
            const unsigned* SQ = SQb[cur];
            const unsigned* SK = SKb[cur];
            #pragma unroll
            for (int kq = 0; kq < 2; kq++) {
                uint2 aA = *(const uint2*)&SQ[(mr + g) * PITCH_H + kq * 8 + 2 * tig];
                uint2 aB = *(const uint2*)&SQ[(mr + g + 8) * PITCH_H + kq * 8 + 2 * tig];
                unsigned a[4] = {aA.x, aB.x, aA.y, aB.y};
                #pragma unroll
                for (int nt = 0; nt < 8; nt++) {
                    uint2 bb = *(const uint2*)&SK[(nt * 8 + g) * PITCH_H + kq * 8 + 2 * tig];
                    unsigned bf[2] = {bb.x, bb.y};
                    mma_f16(c[nt], a, bf);
                }
            }
            __syncthreads();
        }
        // ---- key-padding ----
        #pragma unroll
        for (int nt = 0; nt < 8; nt++) {
            int col = s0 + nt * 8 + tig * 2;
            if (kpb[col])     { c[nt][0] = -1e9f; c[nt][2] = -1e9f; }
            if (kpb[col + 1]) { c[nt][1] = -1e9f; c[nt][3] = -1e9f; }
        }
        // ---- running max + rescale ----
        float mx0 = -1e30f, mx1 = -1e30f;
        #pragma unroll
        for (int nt = 0; nt < 8; nt++) {
            mx0 = fmaxf(mx0, fmaxf(c[nt][0], c[nt][1]));
            mx1 = fmaxf(mx1, fmaxf(c[nt][2], c[nt][3]));
        }
        mx0 = fmaxf(mx0, __shfl_xor_sync(0xffffffffu, mx0, 1));
        mx0 = fmaxf(mx0, __shfl_xor_sync(0xffffffffu, mx0, 2));
        mx1 = fmaxf(mx1, __shfl_xor_sync(0xffffffffu, mx1, 1));
        mx1 = fmaxf(mx1, __shfl_xor_sync(0xffffffffu, mx1, 2));
        float nm0 = fmaxf(m0, mx0), nm1 = fmaxf(m1, mx1);
        float al0 = ex2f(m0 - nm0), al1 = ex2f(m1 - nm1);
        m0 = nm0; m1 = nm1;
        if (al0 != 1.f || al1 != 1.f) {
            l0 *= al0; l1 *= al1;
            #pragma unroll
            for (int nt = 0; nt < 8; nt++) {
                o0[nt][0] *= al0; o0[nt][1] *= al0; o0[nt][2] *= al1; o0[nt][3] *= al1;
                o1[nt][0] *= al0; o1[nt][1] *= al0; o1[nt][2] *= al1; o1[nt][3] *= al1;
            }
        }
        // ---- exp: P stays in registers as PV A-fragments ----
        float rs0 = 0.f, rs1 = 0.f;
        unsigned pa[4][4];
        #pragma unroll
        for (int K = 0; K < 4; K++) {
            float e0a = ex2f(c[2 * K][0] - m0),     e1a = ex2f(c[2 * K][1] - m0);
            float e2a = ex2f(c[2 * K][2] - m1),     e3a = ex2f(c[2 * K][3] - m1);
            float e0b = ex2f(c[2 * K + 1][0] - m0), e1b = ex2f(c[2 * K + 1][1] - m0);
            float e2b = ex2f(c[2 * K + 1][2] - m1), e3b = ex2f(c[2 * K + 1][3] - m1);
            rs0 += e0a + e1a + e0b + e1b;
            rs1 += e2a + e3a + e2b + e3b;
            __half2 hh;
            hh = __floats2half2_rn(e0a, e1a); pa[K][0] = *(unsigned*)&hh;
            hh = __floats2half2_rn(e2a, e3a); pa[K][1] = *(unsigned*)&hh;
            hh = __floats2half2_rn(e0b, e1b); pa[K][2] = *(unsigned*)&hh;
            hh = __floats2half2_rn(e2b, e3b); pa[K][3] = *(unsigned*)&hh;
        }
        rs0 += __shfl_xor_sync(0xffffffffu, rs0, 1);
        rs0 += __shfl_xor_sync(0xffffffffu, rs0, 2);
        rs1 += __shfl_xor_sync(0xffffffffu, rs1, 1);
        rs1 += __shfl_xor_sync(0xffffffffu, rs1, 2);
        l0 += rs0; l1 += rs1;
        // ---- PV: 4 k16 steps, B from smem V, A from registers ----
        #pragma unroll
        for (int K = 0; K < 4; K++) {
            const unsigned* V0 = SV + (K >> 1) * CHWH;
            int off = (K & 1) * 8 + 2 * tig;
            #pragma unroll
            for (int nt = 0; nt < 8; nt++) {
                uint2 bb = *(const uint2*)&V0[(nt * 8 + g) * PITCH_H + off];
                unsigned bf[2] = {bb.x, bb.y};
                mma_f16(o0[nt], pa[K], bf);
            }
            if (nd2 == 2) {
                const unsigned* V1 = SV + (2 + (K >> 1)) * CHWH;
                #pragma unroll
                for (int nt = 0; nt < 8; nt++) {
                    uint2 bb = *(const uint2*)&V1[(nt * 8 + g) * PITCH_H + off];
                    unsigned bf[2] = {bb.x, bb.y};
                    mma_f16(o1[nt], pa[K], bf);
                }
            }
        }
        __syncthreads();   // V/Q/K buffers reused next s-tile
    }
    // ---- epilogue ----
    float inv0 = 1.f / l0, inv1 = 1.f / l1;
    size_t rowbase = (size_t)(b * TSEQ + t0 + mr + g) * D_MODEL;
    #pragma unroll
    for (int nt = 0; nt < 8; nt++) {
        int col = dc0 * 64 + nt * 8 + tig * 2;
        size_t r0 = rowbase + col;
        size_t r1 = r0 + (size_t)8 * D_MODEL;
        atomicAdd(&g_ctx[r0],     o0[nt][0] * inv0);
        atomicAdd(&g_ctx[r0 + 1], o0[nt][1] * inv0);
        atomicAdd(&g_ctx[r1],     o0[nt][2] * inv1);
        atomicAdd(&g_ctx[r1 + 1], o0[nt][3] * inv1);
    }
    if (nd2 == 2) {
        #pragma unroll
        for (int nt = 0; nt < 8; nt++) {
            int col = dc0 * 64 + 64 + nt * 8 + tig * 2;
            size_t r0 = rowbase + col;
            size_t r1 = r0 + (size_t)8 * D_MODEL;
            atomicAdd(&g_ctx[r0],     o1[nt][0] * inv0);
            atomicAdd(&g_ctx[r0 + 1], o1[nt][1] * inv0);
            atomicAdd(&g_ctx[r1],     o1[nt][2] * inv1);
            atomicAdd(&g_ctx[r1 + 1], o1[nt][3] * inv1);
        }
    }
}

// ---------------- res = ctx @ Wout + bout + query (tf32) ----------------
__device__ __forceinline__ void mma_tile_kn(float c[2][4][4], const unsigned* As, const unsigned* Bs,
                                            int wm, int wn, int g, int tig) {
    #pragma unroll
    for (int kq = 0; kq < 32; kq += 8) {
        unsigned a[2][4], b[4][2];
        #pragma unroll
        for (int mt = 0; mt < 2; mt++) {
            int mr = wm * 32 + mt * 16;
            a[mt][0] = As[(mr + g) * PITCH_MK + kq + tig];
            a[mt][1] = As[(mr + g + 8) * PITCH_MK + kq + tig];
            a[mt][2] = As[(mr + g) * PITCH_MK + kq + tig + 4];
            a[mt][3] = As[(mr + g + 8) * PITCH_MK + kq + tig + 4];
        }
        #pragma unroll
        for (int nt = 0; nt < 4; nt++) {
            int nr = wn * 32 + nt * 8;
            b[nt][0] = Bs[(kq + tig) * PITCH_KN + nr + g];
            b[nt][1] = Bs[(kq + tig + 4) * PITCH_KN + nr + g];
        }
        #pragma unroll
        for (int mt = 0; mt < 2; mt++)
            #pragma unroll
            for (int nt = 0; nt < 4; nt++)
                mma_tf32(c[mt][nt], a[mt], b[nt]);
    }
}

__global__ __launch_bounds__(128) void out_gemm(const float* __restrict__ W,
                                                const float* __restrict__ bias,
                                                const float* __restrict__ query) {
    __shared__ float As[2][64 * PITCH_MK];
    __shared__ float Bs[2][32 * PITCH_KN];
    int bm = blockIdx.y * 64, bn = blockIdx.x * 64;
    int tid = threadIdx.x, w = tid >> 5, lane = tid & 31;
    int wm = w >> 1, wn = w & 1, g = lane >> 2, tig = lane & 3;
    float c[2][4][4] = {};
    const float* Abase = g_ctx + (size_t)bm * D_MODEL;
    const float* Wbase = W + bn;
    auto issue = [&](int buf, int k0) {
        #pragma unroll
        for (int it = 0; it < 4; it++) {
            int i = tid + it * 128;
            int r = i >> 3, q = (i & 7) * 4;
            cp16(&As[buf][r * PITCH_MK + q], Abase + (size_t)r * D_MODEL + k0 + q);
        }
        #pragma unroll
        for (int it = 0; it < 4; it++) {
            int i = tid + it * 128;
            int k = i >> 4, q = (i & 15) * 4;
            cp16(&Bs[buf][k * PITCH_KN + q], Wbase + (size_t)(k0 + k) * D_MODEL + q);
        }
    };
    issue(0, 0); CP_COMMIT;
    const int NCH = D_MODEL / 32;
    for (int ci = 0; ci < NCH; ci++) {
        int cur = ci & 1;
        if (ci + 1 < NCH) { issue(cur ^ 1, (ci + 1) * 32); CP_COMMIT; CP_WAIT1; }
        else CP_WAIT0;
        __syncthreads();
        mma_tile_kn(c, (const unsigned*)As[cur], (const unsigned*)Bs[cur], wm, wn, g, tig);
        __syncthreads();
    }
    #pragma unroll
    for (int mt = 0; mt < 2; mt++)
        #pragma unroll
        for (int nt = 0; nt < 4; nt++) {
            int row = bm + wm * 32 + mt * 16 + g;
            int col = bn + wn * 32 + nt * 8 + tig * 2;
            size_t i0 = (size_t)row * D_MODEL + col;
            size_t i2 = (size_t)(row + 8) * D_MODEL + col;
            g_res[i0]     = c[mt][nt][0] + bias[col]     + query[i0];
            g_res[i0 + 1] = c[mt][nt][1] + bias[col + 1] + query[i0 + 1];
            g_res[i2]     = c[mt][nt][2] + bias[col]     + query[i2];
            g_res[i2 + 1] = c[mt][nt][3] + bias[col + 1] + query[i2 + 1];
        }
}

// ---------------- layernorm ----------------
__global__ void ln_kernel(const float* __restrict__ gamma, const float* __restrict__ beta,
                          float* __restrict__ out) {
    __shared__ float shs[8];
    __shared__ float shq[8];
    int row = blockIdx.x;
    const float* x = g_res + (size_t)row * D_MODEL;
    int tid = threadIdx.x;
    float v0 = x[tid], v1 = x[tid + 256];
    float s = v0 + v1, sq = v0 * v0 + v1 * v1;
    #pragma unroll
    for (int o = 16; o > 0; o >>= 1) {
        s  += __shfl_xor_sync(0xffffffffu, s, o);
        sq += __shfl_xor_sync(0xffffffffu, sq, o);
    }
    if ((tid & 31) == 0) { shs[tid >> 5] = s; shq[tid >> 5] = sq; }
    __syncthreads();
    s = 0.f; sq = 0.f;
    #pragma unroll
    for (int w = 0; w < 8; w++) { s += shs[w]; sq += shq[w]; }
    float mu = s * (1.f / D_MODEL);
    float var = sq * (1.f / D_MODEL) - mu * mu;
    float inv = rsqrtf(var + 1e-5f);
    out[(size_t)row * D_MODEL + tid]       = (v0 - mu) * inv * gamma[tid] + beta[tid];
    out[(size_t)row * D_MODEL + tid + 256] = (v1 - mu) * inv * gamma[tid + 256] + beta[tid + 256];
}

// ---------------- launch ----------------
extern "C" void kernel_launch(void* const* d_in, const int* in_sizes, int n_in,
                              void* d_out, int out_size) {
    const float*         query = (const float*)d_in[0];
    const float*         hw    = (const float*)d_in[1];
    const float*         Wqkv  = (const float*)d_in[2];
    const float*         bqkv  = (const float*)d_in[3];
    const float*         Wout  = (const float*)d_in[4];
    const float*         bout  = (const float*)d_in[5];
    const float*         gamma = (const float*)d_in[6];
    const float*         beta  = (const float*)d_in[7];
    const unsigned char* kpm   = (const unsigned char*)d_in[8];
    float* out = (float*)d_out;

    cudaFuncSetAttribute(flash_kernel, cudaFuncAttributeMaxDynamicSharedMemorySize, FLASH_SMEM);

    prep_kernel<<<1 + 64 + 192, 256>>>(hw, query, Wqkv);                // 0
    qkv_gemm<<<dim3(N3 / 64, M_TOTAL / 64), 128>>>(bqkv);               // 1
    pack_all<<<512 + 4096 + 2048, 256>>>();                             // 2
    flash_kernel<<<dim3(4, TSEQ / 64, NHEADS * BATCH), 128, FLASH_SMEM>>>(kpm);  // 3 (profiled)
    out_gemm<<<dim3(D_MODEL / 64, M_TOTAL / 64), 128>>>(Wout, bout, query);      // 4
    ln_kernel<<<M_TOTAL, 256>>>(gamma, beta, out);                      // 5
}

// round 14
// speedup vs baseline: 1.2270x; 1.0731x over previous
#include <cuda_runtime.h>
#include <cuda_fp16.h>
#include <math.h>
#include <stdint.h>

#define D_MODEL 512
#define NHEADS  8
#define TSEQ    1024
#define BATCH   4
#define M_TOTAL 4096
#define N3      1536
#define KSTR    448      /* halves per packed flash row */
#define DCHUNKS 8

#define PITCH_H  24      /* fp16 chunk pitch in uint words (16 data + 8 pad), conflict-free */
#define PITCH_MK 36
#define PITCH_KN 72
#define CHWH     (64 * PITCH_H)  /* 1536 words / 6KB chunk */
/* flash: 2 Q + 2 K + 4 V = 8 chunks * 6144B = 49152B -> 4 CTA/SM */
#define FLASH_SMEM (8 * CHWH * 4)
#define LOG2E 1.4426950408889634f

// ---------------- scratch ----------------
__device__ float  g_qkv[(size_t)M_TOTAL * N3];
__device__ float  g_ctx[(size_t)M_TOTAL * D_MODEL];
__device__ float  g_res[(size_t)M_TOTAL * D_MODEL];
__device__ __half g_qh[(size_t)M_TOTAL * D_MODEL];    // query fp16 [m][k] permuted
__device__ __half g_wh[(size_t)N3 * D_MODEL];         // Wqkv^T fp16 [n][k] permuted
__device__ __half g_qp[(size_t)NHEADS * M_TOTAL * KSTR];
__device__ __half g_kp[(size_t)NHEADS * M_TOTAL * KSTR];
__device__ __half g_vp[(size_t)NHEADS * DCHUNKS * BATCH * 64 * TSEQ];
__device__ float  g_mask[NHEADS][D_MODEL];
__device__ float  g_inv_scale[NHEADS];
__device__ int    g_lo[NHEADS];
__device__ int    g_hi[NHEADS];
__device__ unsigned g_kpb[BATCH][TSEQ / 32];          // key-padding bitmask

// ---------------- helpers ----------------
__device__ __forceinline__ float ex2f(float x) {
    float y; asm("ex2.approx.f32 %0, %1;\n" : "=f"(y) : "f"(x)); return y;
}
__device__ __forceinline__ void mma_tf32(float d[4], const unsigned a[4], const unsigned b[2]) {
    asm volatile(
        "mma.sync.aligned.m16n8k8.row.col.f32.tf32.tf32.f32 "
        "{%0,%1,%2,%3}, {%4,%5,%6,%7}, {%8,%9}, {%0,%1,%2,%3};\n"
        : "+f"(d[0]), "+f"(d[1]), "+f"(d[2]), "+f"(d[3])
        : "r"(a[0]), "r"(a[1]), "r"(a[2]), "r"(a[3]), "r"(b[0]), "r"(b[1]));
}
__device__ __forceinline__ void mma_f16(float d[4], const unsigned a[4], const unsigned b[2]) {
    asm volatile(
        "mma.sync.aligned.m16n8k16.row.col.f32.f16.f16.f32 "
        "{%0,%1,%2,%3}, {%4,%5,%6,%7}, {%8,%9}, {%0,%1,%2,%3};\n"
        : "+f"(d[0]), "+f"(d[1]), "+f"(d[2]), "+f"(d[3])
        : "r"(a[0]), "r"(a[1]), "r"(a[2]), "r"(a[3]), "r"(b[0]), "r"(b[1]));
}
__device__ __forceinline__ void cp16(void* s, const void* gm) {
    unsigned sa = (unsigned)__cvta_generic_to_shared(s);
    asm volatile("cp.async.cg.shared.global [%0], [%1], 16;\n" :: "r"(sa), "l"(gm));
}
#define CP_COMMIT asm volatile("cp.async.commit_group;\n")
#define CP_WAIT0  asm volatile("cp.async.wait_group 0;\n")
#define CP_WAIT1  asm volatile("cp.async.wait_group 1;\n")

// phys word position within an 8-word k-group so fragment pairs land adjacent
__device__ __forceinline__ int permw(int lw) { return 2 * (lw & 3) + (lw >> 2); }

// ---------------- prep + fp16 converts (query, Wqkv^T) + kpm bitmask ----------------
__global__ __launch_bounds__(256) void prep_kernel(const float* __restrict__ hw,
                                                   const float* __restrict__ query,
                                                   const float* __restrict__ Wqkv,
                                                   const unsigned char* __restrict__ kpm) {
    int blk = blockIdx.x;
    int tid = threadIdx.x;
    if (blk == 0) {
        __shared__ float s_start[NHEADS], s_dim[NHEADS];
        if (tid == 0) {
            float m = hw[0];
            for (int h = 1; h < NHEADS; h++) m = fmaxf(m, hw[h]);
            float e[NHEADS]; float sum = 0.f;
            for (int h = 0; h < NHEADS; h++) { e[h] = expf(hw[h] - m); sum += e[h]; }
            float start = 0.f;
            for (int h = 0; h < NHEADS; h++) {
                float gate = e[h] / sum;
                float dim = 16.f + gate * (float)(D_MODEL - 16 * NHEADS);
                if (dim < 0.f) dim = 0.f;
                s_start[h] = start; s_dim[h] = dim;
                g_inv_scale[h] = rsqrtf(dim + 1e-6f);
                start += dim;
            }
        }
        __syncthreads();
        for (int d = tid; d < D_MODEL; d += 256) {
            float pos = (float)d;
            for (int h = 0; h < NHEADS; h++) {
                float l = 1.f / (1.f + expf(-(pos - s_start[h]) * 10.f));
                float r = 1.f / (1.f + expf(-(s_start[h] + s_dim[h] - pos) * 10.f));
                g_mask[h][d] = l * r;
            }
        }
        __syncthreads();
        if (tid == 0) {
            for (int h = 0; h < NHEADS; h++) {
                int lo = D_MODEL, hi = 0;
                for (int d = 0; d < D_MODEL; d++)
                    if (g_mask[h][d] > 1e-6f) { if (d < lo) lo = d; hi = d + 1; }
                if (lo >= hi) { lo = 0; hi = 0; }
                g_lo[h] = lo; g_hi[h] = hi;
            }
        }
        // key-padding bitmask: 4 batches x 32 words
        for (int i = tid; i < BATCH * 32; i += 256) {
            int b = i >> 5, wd = i & 31;
            const unsigned char* p = kpm + b * TSEQ + wd * 32;
            unsigned bits = 0;
            #pragma unroll
            for (int t = 0; t < 32; t++) bits |= (p[t] ? 1u : 0u) << t;
            g_kpb[b][wd] = bits;
        }
    } else if (blk <= 64) {
        // ---- query -> g_qh fp16 [m][k] permuted ----
        int row0 = (blk - 1) * 64;
        for (int i = tid; i < 64 * 128; i += 256) {
            int r = i >> 7, f4 = i & 127;
            float4 v = *(const float4*)(query + (size_t)(row0 + r) * D_MODEL + f4 * 4);
            int k = f4 * 4;
            int chunk = k >> 5, within = k & 31;
            int group = within >> 4, lw = (within & 15) >> 1;
            __half2* dst2 = (__half2*)(g_qh + (size_t)(row0 + r) * D_MODEL);
            int base = chunk * 16 + group * 8;
            dst2[base + permw(lw)]     = __floats2half2_rn(v.x, v.y);
            dst2[base + permw(lw + 1)] = __floats2half2_rn(v.z, v.w);
        }
    } else {
        // ---- Wqkv -> g_wh fp16 [n][k] permuted (transpose via smem) ----
        __shared__ float tile[64][65];
        int j = blk - 65;                  // 192 blocks: 8 k-tiles x 24 n-tiles
        int kt = j & 7, ntile = j >> 3;
        int k0 = kt * 64, n0 = ntile * 64;
        for (int i = tid; i < 64 * 16; i += 256) {
            int kk = i >> 4, nf = (i & 15) * 4;
            float4 v = *(const float4*)(Wqkv + (size_t)(k0 + kk) * N3 + n0 + nf);
            tile[nf][kk]     = v.x;
            tile[nf + 1][kk] = v.y;
            tile[nf + 2][kk] = v.z;
            tile[nf + 3][kk] = v.w;
        }
        __syncthreads();
        for (int i = tid; i < 64 * 32; i += 256) {
            int n = i >> 5, kw = i & 31;
            int kabs = k0 + kw * 2;
            int chunk = kabs >> 5, within = kabs & 31;
            int group = within >> 4, lw = (within & 15) >> 1;
            __half2* dst2 = (__half2*)(g_wh + (size_t)(n0 + n) * D_MODEL);
            dst2[chunk * 16 + group * 8 + permw(lw)] =
                __floats2half2_rn(tile[n][kw * 2], tile[n][kw * 2 + 1]);
        }
    }
}

// ---------------- qkv GEMM; q/k epilogue writes packed fp16 directly ----------------
__global__ __launch_bounds__(128) void qkv_gemm(const float* __restrict__ bias) {
    __shared__ unsigned SA[2][CHWH];
    __shared__ unsigned SB[2][CHWH];
    __shared__ int sLo[NHEADS], sHi[NHEADS];
    __shared__ float sInv[NHEADS];
    int bm = blockIdx.y * 64, bn = blockIdx.x * 64;
    int tid = threadIdx.x, w = tid >> 5, lane = tid & 31;
    int wm = w >> 1, wn = w & 1, g = lane >> 2, tig = lane & 3;
    if (tid < NHEADS) { sLo[tid] = g_lo[tid]; sHi[tid] = g_hi[tid]; sInv[tid] = g_inv_scale[tid]; }
    float c[2][4][4] = {};
    const __half* Abase = g_qh + (size_t)bm * D_MODEL;
    const __half* Bbase = g_wh + (size_t)bn * D_MODEL;
    auto issue = [&](int buf, int ci) {
        #pragma unroll
        for (int it = 0; it < 2; it++) {
            int i = tid + it * 128;
            int r = i >> 2, seg = i & 3;
            cp16(&SA[buf][r * PITCH_H + seg * 4], Abase + (size_t)r * D_MODEL + ci * 32 + seg * 8);
            cp16(&SB[buf][r * PITCH_H + seg * 4], Bbase + (size_t)r * D_MODEL + ci * 32 + seg * 8);
        }
    };
    issue(0, 0); CP_COMMIT;
    const int NCH = D_MODEL / 32;
    for (int ci = 0; ci < NCH; ci++) {
        int cur = ci & 1;
        if (ci + 1 < NCH) { issue(cur ^ 1, ci + 1); CP_COMMIT; CP_WAIT1; }
        else CP_WAIT0;
        __syncthreads();
        const unsigned* A = SA[cur];
        const unsigned* B = SB[cur];
        #pragma unroll
        for (int kq = 0; kq < 2; kq++) {
            unsigned a[2][4], b[4][2];
            #pragma unroll
            for (int mt = 0; mt < 2; mt++) {
                int rowm = wm * 32 + mt * 16;
                uint2 aA = *(const uint2*)&A[(rowm + g) * PITCH_H + kq * 8 + 2 * tig];
                uint2 aB = *(const uint2*)&A[(rowm + g + 8) * PITCH_H + kq * 8 + 2 * tig];
                a[mt][0] = aA.x; a[mt][1] = aB.x; a[mt][2] = aA.y; a[mt][3] = aB.y;
            }
            #pragma unroll
            for (int nt = 0; nt < 4; nt++) {
                int rown = wn * 32 + nt * 8 + g;
                uint2 bb = *(const uint2*)&B[rown * PITCH_H + kq * 8 + 2 * tig];
                b[nt][0] = bb.x; b[nt][1] = bb.y;
            }
            #pragma unroll
            for (int mt = 0; mt < 2; mt++)
                #pragma unroll
                for (int nt = 0; nt < 4; nt++)
                    mma_f16(c[mt][nt], a[mt], b[nt]);
        }
        __syncthreads();
    }
    if (bn >= 2 * D_MODEL) {
        // ---- V: fp32 to g_qkv (pack_v consumes it) ----
        #pragma unroll
        for (int mt = 0; mt < 2; mt++)
            #pragma unroll
            for (int nt = 0; nt < 4; nt++) {
                int row = bm + wm * 32 + mt * 16 + g;
                int col = bn + wn * 32 + nt * 8 + tig * 2;
                g_qkv[(size_t)row * N3 + col]           = c[mt][nt][0] + bias[col];
                g_qkv[(size_t)row * N3 + col + 1]       = c[mt][nt][1] + bias[col + 1];
                g_qkv[(size_t)(row + 8) * N3 + col]     = c[mt][nt][2] + bias[col];
                g_qkv[(size_t)(row + 8) * N3 + col + 1] = c[mt][nt][3] + bias[col + 1];
            }
    } else {
        // ---- Q/K: masked fp16 permuted direct to g_qp/g_kp ----
        int which = (bn >= D_MODEL) ? 1 : 0;
        __half* dstb = which ? g_kp : g_qp;
        #pragma unroll
        for (int mt = 0; mt < 2; mt++)
            #pragma unroll
            for (int nt = 0; nt < 4; nt++) {
                int row = bm + wm * 32 + mt * 16 + g;
                int col = bn + wn * 32 + nt * 8 + tig * 2;
                int d = col - which * D_MODEL;
                float v0 = c[mt][nt][0] + bias[col];
                float v1 = c[mt][nt][1] + bias[col + 1];
                float v2 = c[mt][nt][2] + bias[col];
                float v3 = c[mt][nt][3] + bias[col + 1];
                for (int h = 0; h < NHEADS; h++) {
                    int klo = sLo[h] & ~31;
                    int khi = (sHi[h] + 31) & ~31;
                    if (d < klo || d >= khi) continue;
                    float sc = which ? 1.f : sInv[h] * LOG2E;
                    float mk0 = g_mask[h][d] * sc, mk1 = g_mask[h][d + 1] * sc;
                    int koff = d - klo;
                    int idx = (koff >> 5) * 16 + ((koff & 31) >> 4) * 8 + permw((koff & 15) >> 1);
                    __half2* dA = (__half2*)(dstb + ((size_t)h * M_TOTAL + row) * KSTR);
                    __half2* dB = (__half2*)(dstb + ((size_t)h * M_TOTAL + row + 8) * KSTR);
                    dA[idx] = __floats2half2_rn(v0 * mk0, v1 * mk1);
                    dB[idx] = __floats2half2_rn(v2 * mk0, v3 * mk1);
                }
            }
    }
}

// ---------------- pack_all: pack_v (4096) + zero_ctx (2048) ----------------
__global__ __launch_bounds__(256) void pack_all() {
    __shared__ float tile[64][65];
    int blk = blockIdx.x;
    int tid = threadIdx.x;
    if (blk < 4096) {
        int j = blk;
        int s0 = (j & 15) * 64;
        int b = (j >> 4) & 3;
        int z = j >> 6;
        int h = z >> 3, dc = z & 7;
        int d0 = dc * 64;
        if (g_hi[h] <= d0 || g_lo[h] >= d0 + 64) return;
        const float* mask = g_mask[h];
        const float* vsrc = g_qkv + (size_t)(b * TSEQ + s0) * N3 + 2 * D_MODEL + d0;
        for (int i = tid; i < 64 * 16; i += 256) {
            int s = i >> 4, dseg = (i & 15) * 4;
            float4 v = *(const float4*)(vsrc + (size_t)s * N3 + dseg);
            tile[dseg][s]     = v.x * mask[d0 + dseg];
            tile[dseg + 1][s] = v.y * mask[d0 + dseg + 1];
            tile[dseg + 2][s] = v.z * mask[d0 + dseg + 2];
            tile[dseg + 3][s] = v.w * mask[d0 + dseg + 3];
        }
        __syncthreads();
        __half* dst = g_vp + ((size_t)z * BATCH + b) * 64 * TSEQ;
        for (int i = tid; i < 64 * 32; i += 256) {
            int d = i >> 5, sw = i & 31;
            int chunk = sw >> 4;
            int wv = sw & 15;
            int group = wv >> 3, lw = wv & 7;
            __half2* dst2 = (__half2*)(dst + (size_t)d * TSEQ + s0);
            dst2[chunk * 16 + group * 8 + permw(lw)] =
                __floats2half2_rn(tile[d][2 * sw], tile[d][2 * sw + 1]);
        }
    } else {
        size_t j = (size_t)(blk - 4096) * 256 + tid;
        ((float4*)g_ctx)[j] = make_float4(0.f, 0.f, 0.f, 0.f);
    }
}

// ---------------- flash: fp16, 64 t-rows, 128 thr, 4 CTA/SM, P in regs, kpm bitmask ----
__global__ __launch_bounds__(128, 4) void flash_kernel() {
    extern __shared__ unsigned sm[];
    unsigned* SQb[2] = { sm,            sm + CHWH };
    unsigned* SKb[2] = { sm + 2 * CHWH, sm + 3 * CHWH };
    unsigned* SV = sm + 4 * CHWH;                // 4 V bufs (2 d-chunks x 2 s-halves)
    int z = blockIdx.z, h = z >> 2, b = z & 3;
    int t0 = blockIdx.y * 64;
    int dclo = g_lo[h] >> 6, dchi = (g_hi[h] - 1) >> 6;
    int dc0 = dclo + 2 * blockIdx.x;
    if (dc0 > dchi) return;
    int nd2 = (dc0 + 1 <= dchi) ? 2 : 1;
    int klo = g_lo[h] & ~31;
    int khi = (g_hi[h] + 31) & ~31; if (khi > D_MODEL) khi = D_MODEL;
    int nch = (khi - klo) >> 5;
    const __half* qp  = g_qp + ((size_t)h * M_TOTAL + b * TSEQ + t0) * KSTR;
    const __half* kp  = g_kp + ((size_t)h * M_TOTAL + b * TSEQ) * KSTR;
    const __half* vp0 = g_vp + ((size_t)(h * 8 + dc0) * BATCH + b) * 64 * TSEQ;
    const __half* vp1 = g_vp + ((size_t)(h * 8 + dc0 + 1) * BATCH + b) * 64 * TSEQ;
    int tid = threadIdx.x, w = tid >> 5, lane = tid & 31, g = lane >> 2, tig = lane & 3;
    int mr = w * 16;

    float o0[8][4] = {}, o1[8][4] = {};
    float m0 = -1e30f, m1 = -1e30f, l0 = 0.f, l1 = 0.f;

    for (int s0 = 0; s0 < TSEQ; s0 += 64) {
        // V prefetch
        #pragma unroll
        for (int half = 0; half < 2; half++)
            #pragma unroll
            for (int it = 0; it < 2; it++) {
                int i = tid + it * 128;
                int r = i >> 2, seg = i & 3;
                cp16(&SV[half * CHWH + r * PITCH_H + seg * 4],
                     vp0 + (size_t)r * TSEQ + s0 + half * 32 + seg * 8);
            }
        if (nd2 == 2)
            #pragma unroll
            for (int half = 0; half < 2; half++)
                #pragma unroll
                for (int it = 0; it < 2; it++) {
                    int i = tid + it * 128;
                    int r = i >> 2, seg = i & 3;
                    cp16(&SV[(2 + half) * CHWH + r * PITCH_H + seg * 4],
                         vp1 + (size_t)r * TSEQ + s0 + half * 32 + seg * 8);
                }
        CP_COMMIT;

        auto issue_chunk = [&](int buf, int ci) {
            #pragma unroll
            for (int it = 0; it < 2; it++) {
                int i = tid + it * 128;
                int r = i >> 2, seg = i & 3;
                cp16(&SKb[buf][r * PITCH_H + seg * 4], kp + (size_t)(s0 + r) * KSTR + ci * 32 + seg * 8);
                cp16(&SQb[buf][r * PITCH_H + seg * 4], qp + (size_t)r * KSTR + ci * 32 + seg * 8);
            }
        };
        issue_chunk(0, 0); CP_COMMIT;

        // ---- S = Qm . Km (fp16 MMA, log2-scaled) ----
        float c[8][4] = {};
        for (int ci = 0; ci < nch; ci++) {
            int cur = ci & 1;
            if (ci + 1 < nch) { issue_chunk(cur ^ 1, ci + 1); CP_COMMIT; CP_WAIT1; }
            else CP_WAIT0;
            __syncthreads();
            const unsigned* SQ = SQb[cur];
            const unsigned* SK = SKb[cur];
            #pragma unroll
            for (int kq = 0; kq < 2; kq++) {
                uint2 aA = *(const uint2*)&SQ[(mr + g) * PITCH_H + kq * 8 + 2 * tig];
                uint2 aB = *(const uint2*)&SQ[(mr + g + 8) * PITCH_H + kq * 8 + 2 * tig];
                unsigned a[4] = {aA.x, aB.x, aA.y, aB.y};
                #pragma unroll
                for (int nt = 0; nt < 8; nt++) {
                    uint2 bb = *(const uint2*)&SK[(nt * 8 + g) * PITCH_H + kq * 8 + 2 * tig];
                    unsigned bf[2] = {bb.x, bb.y};
                    mma_f16(c[nt], a, bf);
                }
            }
            __syncthreads();
        }
        // ---- key-padding via bitmask (uniform fast-path) ----
        unsigned kw0 = g_kpb[b][s0 >> 5], kw1 = g_kpb[b][(s0 >> 5) + 1];
        if (kw0 | kw1) {
            #pragma unroll
            for (int nt = 0; nt < 8; nt++) {
                int off = nt * 8 + tig * 2;
                unsigned wsel = (off & 32) ? kw1 : kw0;
                int sh = off & 31;
                if ((wsel >> sh) & 1)       { c[nt][0] = -1e9f; c[nt][2] = -1e9f; }
                if ((wsel >> (sh + 1)) & 1) { c[nt][1] = -1e9f; c[nt][3] = -1e9f; }
            }
        }
        // ---- running max + rescale ----
        float mx0 = -1e30f, mx1 = -1e30f;
        #pragma unroll
        for (int nt = 0; nt < 8; nt++) {
            mx0 = fmaxf(mx0, fmaxf(c[nt][0], c[nt][1]));
            mx1 = fmaxf(mx1, fmaxf(c[nt][2], c[nt][3]));
        }
        mx0 = fmaxf(mx0, __shfl_xor_sync(0xffffffffu, mx0, 1));
        mx0 = fmaxf(mx0, __shfl_xor_sync(0xffffffffu, mx0, 2));
        mx1 = fmaxf(mx1, __shfl_xor_sync(0xffffffffu, mx1, 1));
        mx1 = fmaxf(mx1, __shfl_xor_sync(0xffffffffu, mx1, 2));
        float nm0 = fmaxf(m0, mx0), nm1 = fmaxf(m1, mx1);
        float al0 = ex2f(m0 - nm0), al1 = ex2f(m1 - nm1);
        m0 = nm0; m1 = nm1;
        if (al0 != 1.f || al1 != 1.f) {
            l0 *= al0; l1 *= al1;
            #pragma unroll
            for (int nt = 0; nt < 8; nt++) {
                o0[nt][0] *= al0; o0[nt][1] *= al0; o0[nt][2] *= al1; o0[nt][3] *= al1;
                o1[nt][0] *= al0; o1[nt][1] *= al0; o1[nt][2] *= al1; o1[nt][3] *= al1;
            }
        }
        // ---- exp: P stays in registers as PV A-fragments ----
        float rs0 = 0.f, rs1 = 0.f;
        unsigned pa[4][4];
        #pragma unroll
        for (int K = 0; K < 4; K++) {
            float e0a = ex2f(c[2 * K][0] - m0),     e1a = ex2f(c[2 * K][1] - m0);
            float e2a = ex2f(c[2 * K][2] - m1),     e3a = ex2f(c[2 * K][3] - m1);
            float e0b = ex2f(c[2 * K + 1][0] - m0), e1b = ex2f(c[2 * K + 1][1] - m0);
            float e2b = ex2f(c[2 * K + 1][2] - m1), e3b = ex2f(c[2 * K + 1][3] - m1);
            rs0 += e0a + e1a + e0b + e1b;
            rs1 += e2a + e3a + e2b + e3b;
            __half2 hh;
            hh = __floats2half2_rn(e0a, e1a); pa[K][0] = *(unsigned*)&hh;
            hh = __floats2half2_rn(e2a, e3a); pa[K][1] = *(unsigned*)&hh;
            hh = __floats2half2_rn(e0b, e1b); pa[K][2] = *(unsigned*)&hh;
            hh = __floats2half2_rn(e2b, e3b); pa[K][3] = *(unsigned*)&hh;
        }
        rs0 += __shfl_xor_sync(0xffffffffu, rs0, 1);
        rs0 += __shfl_xor_sync(0xffffffffu, rs0, 2);
        rs1 += __shfl_xor_sync(0xffffffffu, rs1, 1);
        rs1 += __shfl_xor_sync(0xffffffffu, rs1, 2);
        l0 += rs0; l1 += rs1;
        // ---- PV: 4 k16 steps, B from smem V, A from registers ----
        #pragma unroll
        for (int K = 0; K < 4; K++) {
            const unsigned* V0 = SV + (K >> 1) * CHWH;
            int off = (K & 1) * 8 + 2 * tig;
            #pragma unroll
            for (int nt = 0; nt < 8; nt++) {
                uint2 bb = *(const uint2*)&V0[(nt * 8 + g) * PITCH_H + off];
                unsigned bf[2] = {bb.x, bb.y};
                mma_f16(o0[nt], pa[K], bf);
            }
            if (nd2 == 2) {
                const unsigned* V1 = SV + (2 + (K >> 1)) * CHWH;
                #pragma unroll
                for (int nt = 0; nt < 8; nt++) {
                    uint2 bb = *(const uint2*)&V1[(nt * 8 + g) * PITCH_H + off];
                    unsigned bf[2] = {bb.x, bb.y};
                    mma_f16(o1[nt], pa[K], bf);
                }
            }
        }
        __syncthreads();   // V/Q/K buffers reused next s-tile
    }
    // ---- epilogue ----
    float inv0 = 1.f / l0, inv1 = 1.f / l1;
    size_t rowbase = (size_t)(b * TSEQ + t0 + mr + g) * D_MODEL;
    #pragma unroll
    for (int nt = 0; nt < 8; nt++) {
        int col = dc0 * 64 + nt * 8 + tig * 2;
        size_t r0 = rowbase + col;
        size_t r1 = r0 + (size_t)8 * D_MODEL;
        atomicAdd(&g_ctx[r0],     o0[nt][0] * inv0);
        atomicAdd(&g_ctx[r0 + 1], o0[nt][1] * inv0);
        atomicAdd(&g_ctx[r1],     o0[nt][2] * inv1);
        atomicAdd(&g_ctx[r1 + 1], o0[nt][3] * inv1);
    }
    if (nd2 == 2) {
        #pragma unroll
        for (int nt = 0; nt < 8; nt++) {
            int col = dc0 * 64 + 64 + nt * 8 + tig * 2;
            size_t r0 = rowbase + col;
            size_t r1 = r0 + (size_t)8 * D_MODEL;
            atomicAdd(&g_ctx[r0],     o1[nt][0] * inv0);
            atomicAdd(&g_ctx[r0 + 1], o1[nt][1] * inv0);
            atomicAdd(&g_ctx[r1],     o1[nt][2] * inv1);
            atomicAdd(&g_ctx[r1 + 1], o1[nt][3] * inv1);
        }
    }
}

// ---------------- res = ctx @ Wout + bout + query (tf32) ----------------
__device__ __forceinline__ void mma_tile_kn(float c[2][4][4], const unsigned* As, const unsigned* Bs,
                                            int wm, int wn, int g, int tig) {
    #pragma unroll
    for (int kq = 0; kq < 32; kq += 8) {
        unsigned a[2][4], b[4][2];
        #pragma unroll
        for (int mt = 0; mt < 2; mt++) {
            int mr = wm * 32 + mt * 16;
            a[mt][0] = As[(mr + g) * PITCH_MK + kq + tig];
            a[mt][1] = As[(mr + g + 8) * PITCH_MK + kq + tig];
            a[mt][2] = As[(mr + g) * PITCH_MK + kq + tig + 4];
            a[mt][3] = As[(mr + g + 8) * PITCH_MK + kq + tig + 4];
        }
        #pragma unroll
        for (int nt = 0; nt < 4; nt++) {
            int nr = wn * 32 + nt * 8;
            b[nt][0] = Bs[(kq + tig) * PITCH_KN + nr + g];
            b[nt][1] = Bs[(kq + tig + 4) * PITCH_KN + nr + g];
        }
        #pragma unroll
        for (int mt = 0; mt < 2; mt++)
            #pragma unroll
            for (int nt = 0; nt < 4; nt++)
                mma_tf32(c[mt][nt], a[mt], b[nt]);
    }
}

__global__ __launch_bounds__(128) void out_gemm(const float* __restrict__ W,
                                                const float* __restrict__ bias,
                                                const float* __restrict__ query) {
    __shared__ float As[2][64 * PITCH_MK];
    __shared__ float Bs[2][32 * PITCH_KN];
    int bm = blockIdx.y * 64, bn = blockIdx.x * 64;
    int tid = threadIdx.x, w = tid >> 5, lane = tid & 31;
    int wm = w >> 1, wn = w & 1, g = lane >> 2, tig = lane & 3;
    float c[2][4][4] = {};
    const float* Abase = g_ctx + (size_t)bm * D_MODEL;
    const float* Wbase = W + bn;
    auto issue = [&](int buf, int k0) {
        #pragma unroll
        for (int it = 0; it < 4; it++) {
            int i = tid + it * 128;
            int r = i >> 3, q = (i & 7) * 4;
            cp16(&As[buf][r * PITCH_MK + q], Abase + (size_t)r * D_MODEL + k0 + q);
        }
        #pragma unroll
        for (int it = 0; it < 4; it++) {
            int i = tid + it * 128;
            int k = i >> 4, q = (i & 15) * 4;
            cp16(&Bs[buf][k * PITCH_KN + q], Wbase + (size_t)(k0 + k) * D_MODEL + q);
        }
    };
    issue(0, 0); CP_COMMIT;
    const int NCH = D_MODEL / 32;
    for (int ci = 0; ci < NCH; ci++) {
        int cur = ci & 1;
        if (ci + 1 < NCH) { issue(cur ^ 1, (ci + 1) * 32); CP_COMMIT; CP_WAIT1; }
        else CP_WAIT0;
        __syncthreads();
        mma_tile_kn(c, (const unsigned*)As[cur], (const unsigned*)Bs[cur], wm, wn, g, tig);
        __syncthreads();
    }
    #pragma unroll
    for (int mt = 0; mt < 2; mt++)
        #pragma unroll
        for (int nt = 0; nt < 4; nt++) {
            int row = bm + wm * 32 + mt * 16 + g;
            int col = bn + wn * 32 + nt * 8 + tig * 2;
            size_t i0 = (size_t)row * D_MODEL + col;
            size_t i2 = (size_t)(row + 8) * D_MODEL + col;
            g_res[i0]     = c[mt][nt][0] + bias[col]     + query[i0];
            g_res[i0 + 1] = c[mt][nt][1] + bias[col + 1] + query[i0 + 1];
            g_res[i2]     = c[mt][nt][2] + bias[col]     + query[i2];
            g_res[i2 + 1] = c[mt][nt][3] + bias[col + 1] + query[i2 + 1];
        }
}

// ---------------- layernorm ----------------
__global__ void ln_kernel(const float* __restrict__ gamma, const float* __restrict__ beta,
                          float* __restrict__ out) {
    __shared__ float shs[8];
    __shared__ float shq[8];
    int row = blockIdx.x;
    const float* x = g_res + (size_t)row * D_MODEL;
    int tid = threadIdx.x;
    float v0 = x[tid], v1 = x[tid + 256];
    float s = v0 + v1, sq = v0 * v0 + v1 * v1;
    #pragma unroll
    for (int o = 16; o > 0; o >>= 1) {
        s  += __shfl_xor_sync(0xffffffffu, s, o);
        sq += __shfl_xor_sync(0xffffffffu, sq, o);
    }
    if ((tid & 31) == 0) { shs[tid >> 5] = s; shq[tid >> 5] = sq; }
    __syncthreads();
    s = 0.f; sq = 0.f;
    #pragma unroll
    for (int w = 0; w < 8; w++) { s += shs[w]; sq += shq[w]; }
    float mu = s * (1.f / D_MODEL);
    float var = sq * (1.f / D_MODEL) - mu * mu;
    float inv = rsqrtf(var + 1e-5f);
    out[(size_t)row * D_MODEL + tid]       = (v0 - mu) * inv * gamma[tid] + beta[tid];
    out[(size_t)row * D_MODEL + tid + 256] = (v1 - mu) * inv * gamma[tid + 256] + beta[tid + 256];
}

// ---------------- launch ----------------
extern "C" void kernel_launch(void* const* d_in, const int* in_sizes, int n_in,
                              void* d_out, int out_size) {
    const float*         query = (const float*)d_in[0];
    const float*         hw    = (const float*)d_in[1];
    const float*         Wqkv  = (const float*)d_in[2];
    const float*         bqkv  = (const float*)d_in[3];
    const float*         Wout  = (const float*)d_in[4];
    const float*         bout  = (const float*)d_in[5];
    const float*         gamma = (const float*)d_in[6];
    const float*         beta  = (const float*)d_in[7];
    const unsigned char* kpm   = (const unsigned char*)d_in[8];
    float* out = (float*)d_out;

    cudaFuncSetAttribute(flash_kernel, cudaFuncAttributeMaxDynamicSharedMemorySize, FLASH_SMEM);

    prep_kernel<<<1 + 64 + 192, 256>>>(hw, query, Wqkv, kpm);           // 0
    qkv_gemm<<<dim3(N3 / 64, M_TOTAL / 64), 128>>>(bqkv);               // 1
    pack_all<<<4096 + 2048, 256>>>();                                   // 2
    flash_kernel<<<dim3(4, TSEQ / 64, NHEADS * BATCH), 128, FLASH_SMEM>>>();  // 3 (profiled)
    out_gemm<<<dim3(D_MODEL / 64, M_TOTAL / 64), 128>>>(Wout, bout, query);   // 4
    ln_kernel<<<M_TOTAL, 256>>>(gamma, beta, out);                      // 5
}